// round 3
// baseline (speedup 1.0000x reference)
#include <cuda_runtime.h>
#include <cuda_bf16.h>
#include <cstdint>

// ---------------------------------------------------------------------------
// ConvAttention: key/query conv projections -> squared-L2 scores ->
// log_softmax + log prior (attn_logprob) -> masked softmax (attn).
// Shapes: B=8, Cm=80, T1=800, Ct=512, T2=200, Ca=80.
// Output: [attn (8*800*200), attn_logprob (8*800*200)] fp32.
// ---------------------------------------------------------------------------

#define Bn   8
#define T1n  800
#define T2n  200
#define Can  80

// Scratch (device globals; no allocation allowed)
__device__ float g_hidK[8 * 1024 * 200];   // key conv1 output (+ReLU)
__device__ float g_ke  [8 * 80   * 200];   // key embedding
__device__ float g_hidQ1[8 * 160 * 800];   // query conv1 (+ReLU)
__device__ float g_hidQ2[8 * 80  * 800];   // query conv2 (+ReLU)
__device__ float g_qe  [8 * 80   * 800];   // query embedding

// ---------------------------------------------------------------------------
// Generic 1-D conv as tiled GEMM.
//   Y[b, m, t] = act( bias[m] + sum_{ci, tap} W[m, ci, tap] * X[b, ci, t + tap - PAD] )
// Tile: BM = TM*8 rows (out channels) x BN=64 cols (time). 128 threads,
// each computes TM x 4 outputs in registers. K (Cin) chunked by BK=16.
// ---------------------------------------------------------------------------
template <int NTAPS, bool RELU, int TM>
__global__ void __launch_bounds__(128)
conv_gemm_kernel(const float* __restrict__ X, const float* __restrict__ W,
                 const float* __restrict__ bias, float* __restrict__ Y,
                 int M, int N, int Cin)
{
    constexpr int PAD = (NTAPS - 1) / 2;
    constexpr int BM = TM * 8;
    constexpr int BN = 64;
    constexpr int BK = 16;
    constexpr int TN = 4;

    __shared__ float sA[NTAPS][BK][BM];
    __shared__ float sB[BK][BN + 2];

    const int b  = blockIdx.z;
    const int m0 = blockIdx.y * BM;
    const int n0 = blockIdx.x * BN;
    const float* Xb = X + (size_t)b * Cin * N;

    const int tid = threadIdx.x;
    const int tx  = tid & 15;   // 16 column groups (TN=4 each)
    const int ty  = tid >> 4;   // 8 row groups (TM each)

    float acc[TM][TN];
#pragma unroll
    for (int r = 0; r < TM; r++)
#pragma unroll
        for (int u = 0; u < TN; u++) acc[r][u] = 0.f;

    for (int c0 = 0; c0 < Cin; c0 += BK) {
        // --- load W tile: sA[tap][ci][mi] ---
        for (int idx = tid; idx < BM * BK * NTAPS; idx += 128) {
            int mi  = idx / (BK * NTAPS);
            int r   = idx - mi * (BK * NTAPS);
            int ci  = r / NTAPS;
            int tap = r - ci * NTAPS;
            int m   = m0 + mi;
            float v = (m < M) ? W[((size_t)m * Cin + (c0 + ci)) * NTAPS + tap] : 0.f;
            sA[tap][ci][mi] = v;
        }
        // --- load X tile with halo: sB[ci][tl], global t = n0 - PAD + tl ---
        for (int idx = tid; idx < BK * (BN + 2); idx += 128) {
            int ci = idx / (BN + 2);
            int tl = idx - ci * (BN + 2);
            int t  = n0 - PAD + tl;
            float v = (t >= 0 && t < N) ? Xb[(size_t)(c0 + ci) * N + t] : 0.f;
            sB[ci][tl] = v;
        }
        __syncthreads();

#pragma unroll
        for (int kc = 0; kc < BK; kc++) {
            float bv[TN + NTAPS - 1];
#pragma unroll
            for (int u = 0; u < TN + NTAPS - 1; u++) bv[u] = sB[kc][tx * TN + u];
#pragma unroll
            for (int tap = 0; tap < NTAPS; tap++) {
                float av[TM];
#pragma unroll
                for (int r = 0; r < TM; r++) av[r] = sA[tap][kc][ty * TM + r];
#pragma unroll
                for (int r = 0; r < TM; r++)
#pragma unroll
                    for (int u = 0; u < TN; u++)
                        acc[r][u] = fmaf(av[r], bv[u + tap], acc[r][u]);
            }
        }
        __syncthreads();
    }

    // --- epilogue ---
#pragma unroll
    for (int r = 0; r < TM; r++) {
        int m = m0 + ty * TM + r;
        if (m >= M) break;
        float bi = bias[m];
#pragma unroll
        for (int u = 0; u < TN; u++) {
            int t = n0 + tx * TN + u;
            if (t < N) {
                float v = acc[r][u] + bi;
                if (RELU) v = fmaxf(v, 0.f);
                Y[((size_t)b * M + m) * N + t] = v;
            }
        }
    }
}

// ---------------------------------------------------------------------------
// Fused attention kernel: one block per (b, i).
// score[j] = -5e-4 * sum_c (qe[b,c,i] - ke[b,c,j])^2
// attn_logprob = score - logsumexp_j(score) + log(prior + 1e-8)
// attn = softmax_j( masked attn_logprob )
// mask read as 32-bit words (valid for int32 or float32 encodings of bool).
// ---------------------------------------------------------------------------
__global__ void __launch_bounds__(256)
attn_kernel(const float* __restrict__ qe, const float* __restrict__ ke,
            const float* __restrict__ prior, const unsigned* __restrict__ mask,
            float* __restrict__ out)
{
    const int b = blockIdx.y;
    const int i = blockIdx.x;
    __shared__ float q[Can];
    __shared__ float red[256];
    const int tid = threadIdx.x;

    if (tid < Can) q[tid] = qe[((size_t)b * Can + tid) * T1n + i];
    __syncthreads();

    const bool valid = tid < T2n;
    float sc = -1e30f;
    if (valid) {
        const float* kp = ke + (size_t)b * Can * T2n + tid;
        float d = 0.f;
#pragma unroll 10
        for (int c = 0; c < Can; c++) {
            float t = q[c] - kp[(size_t)c * T2n];
            d = fmaf(t, t, d);
        }
        sc = -5e-4f * d;
    }

    // logsumexp over j
    red[tid] = sc; __syncthreads();
    for (int s = 128; s > 0; s >>= 1) { if (tid < s) red[tid] = fmaxf(red[tid], red[tid + s]); __syncthreads(); }
    float mx = red[0]; __syncthreads();
    red[tid] = valid ? __expf(sc - mx) : 0.f; __syncthreads();
    for (int s = 128; s > 0; s >>= 1) { if (tid < s) red[tid] += red[tid + s]; __syncthreads(); }
    float lse = mx + __logf(red[0]); __syncthreads();

    const size_t base = ((size_t)b * T1n + i) * T2n;
    float lp = 0.f;
    if (valid) {
        lp = sc - lse + __logf(prior[base + tid] + 1e-8f);
        out[(size_t)Bn * T1n * T2n + base + tid] = lp;   // attn_logprob half
    }

    const bool keep = valid && (mask[b * T2n + tid] == 0u);
    float ml = keep ? lp : -1e30f;
    red[tid] = ml; __syncthreads();
    for (int s = 128; s > 0; s >>= 1) { if (tid < s) red[tid] = fmaxf(red[tid], red[tid + s]); __syncthreads(); }
    float m2 = red[0]; __syncthreads();
    red[tid] = keep ? __expf(ml - m2) : 0.f; __syncthreads();
    for (int s = 128; s > 0; s >>= 1) { if (tid < s) red[tid] += red[tid + s]; __syncthreads(); }
    float s2 = red[0];

    if (valid) out[base + tid] = keep ? __expf(ml - m2) / s2 : 0.f;  // attn half
}

// ---------------------------------------------------------------------------

static float* sym_addr(const void* sym)
{
    void* p = nullptr;
    cudaGetSymbolAddress(&p, sym);
    return (float*)p;
}

extern "C" void kernel_launch(void* const* d_in, const int* in_sizes, int n_in,
                              void* d_out, int out_size)
{
    const float*    queries = (const float*)d_in[0];   // (8,80,800)
    const float*    keys    = (const float*)d_in[1];   // (8,512,200)
    /* d_in[2] query_lens: unused by the reference computation */
    const unsigned* mask    = (const unsigned*)d_in[3];// (8,200,1) bool->32bit
    const float*    prior   = (const float*)d_in[4];   // (8,800,200)
    const float*    kp_w1   = (const float*)d_in[5];   // (1024,512,3)
    const float*    kp_b1   = (const float*)d_in[6];
    const float*    kp_w2   = (const float*)d_in[7];   // (80,1024,1)
    const float*    kp_b2   = (const float*)d_in[8];
    const float*    qp_w1   = (const float*)d_in[9];   // (160,80,3)
    const float*    qp_b1   = (const float*)d_in[10];
    const float*    qp_w2   = (const float*)d_in[11];  // (80,160,1)
    const float*    qp_b2   = (const float*)d_in[12];
    const float*    qp_w3   = (const float*)d_in[13];  // (80,80,1)
    const float*    qp_b3   = (const float*)d_in[14];
    float* out = (float*)d_out;

    float* hidK  = sym_addr(g_hidK);
    float* ke    = sym_addr(g_ke);
    float* hidQ1 = sym_addr(g_hidQ1);
    float* hidQ2 = sym_addr(g_hidQ2);
    float* qe    = sym_addr(g_qe);

    dim3 blk(128);

    // key proj: conv1d(512->1024,k3,p1)+ReLU ; conv1d(1024->80,k1)
    conv_gemm_kernel<3, true, 8><<<dim3(4, 16, 8), blk>>>(keys, kp_w1, kp_b1, hidK, 1024, 200, 512);
    conv_gemm_kernel<1, false, 4><<<dim3(4, 3, 8), blk>>>(hidK, kp_w2, kp_b2, ke, 80, 200, 1024);

    // query proj: conv1d(80->160,k3,p1)+ReLU ; conv1d(160->80,k1)+ReLU ; conv1d(80->80,k1)
    conv_gemm_kernel<3, true, 4><<<dim3(13, 5, 8), blk>>>(queries, qp_w1, qp_b1, hidQ1, 160, 800, 80);
    conv_gemm_kernel<1, true, 4><<<dim3(13, 3, 8), blk>>>(hidQ1, qp_w2, qp_b2, hidQ2, 80, 800, 160);
    conv_gemm_kernel<1, false, 4><<<dim3(13, 3, 8), blk>>>(hidQ2, qp_w3, qp_b3, qe, 80, 800, 80);

    // fused distance + log_softmax + prior + masked softmax
    attn_kernel<<<dim3(T1n, Bn), 256>>>(qe, ke, prior, mask, out);
}

// round 5
// speedup vs baseline: 1.9622x; 1.9622x over previous
#include <cuda_runtime.h>
#include <cuda_bf16.h>
#include <cstdint>

// ---------------------------------------------------------------------------
// ConvAttention: key/query conv projections -> squared-L2 scores ->
// log_softmax + log prior (attn_logprob) -> masked softmax (attn).
// Shapes: B=8, Cm=80, T1=800, Ct=512, T2=200, Ca=80.
// R4: kp_conv1 on bf16 mma.sync (HMMA) — tcgen05 unavailable (ptx target
// is plain sm_103, arch-specific 'a' features rejected).
// ---------------------------------------------------------------------------

#define Bn   8
#define T1n  800
#define T2n  200
#define Can  80

// Scratch (device globals; no allocation allowed)
__device__ float g_hidK[8 * 1024 * 200];   // key conv1 output (+ReLU)
__device__ float g_ke  [8 * 80   * 200];   // key embedding
__device__ float g_hidQ1[8 * 160 * 800];   // query conv1 (+ReLU)
__device__ float g_hidQ2[8 * 80  * 800];   // query conv2 (+ReLU)
__device__ float g_qe  [8 * 80   * 800];   // query embedding
__device__ __nv_bfloat16 g_wt[3 * 1024 * 512];   // kp_w1 bf16, [tap][m][c]
__device__ __nv_bfloat16 g_xt[8 * 200 * 512];    // keys  bf16, [b][t][c]

// ========================= inline PTX helpers ==============================

__device__ __forceinline__ uint32_t smem_u32(const void* p) {
    uint32_t a;
    asm("{ .reg .u64 t; cvta.to.shared.u64 t, %1; cvt.u32.u64 %0, t; }"
        : "=r"(a) : "l"(p));
    return a;
}

__device__ __forceinline__ void cp16(uint32_t dst, const void* src, int sz) {
    asm volatile("cp.async.cg.shared.global [%0], [%1], 16, %2;"
                 :: "r"(dst), "l"(src), "r"(sz) : "memory");
}
#define CP_COMMIT() asm volatile("cp.async.commit_group;" ::: "memory")

__device__ __forceinline__ void ldmx4(uint32_t* r, uint32_t addr) {
    asm volatile("ldmatrix.sync.aligned.m8n8.x4.shared.b16 {%0,%1,%2,%3}, [%4];"
                 : "=r"(r[0]), "=r"(r[1]), "=r"(r[2]), "=r"(r[3]) : "r"(addr));
}
__device__ __forceinline__ void ldmx2(uint32_t* r, uint32_t addr) {
    asm volatile("ldmatrix.sync.aligned.m8n8.x2.shared.b16 {%0,%1}, [%2];"
                 : "=r"(r[0]), "=r"(r[1]) : "r"(addr));
}

__device__ __forceinline__ void mma16816(float* c, const uint32_t* a, const uint32_t* bq) {
    asm volatile(
        "mma.sync.aligned.m16n8k16.row.col.f32.bf16.bf16.f32 "
        "{%0,%1,%2,%3}, {%4,%5,%6,%7}, {%8,%9}, {%0,%1,%2,%3};"
        : "+f"(c[0]), "+f"(c[1]), "+f"(c[2]), "+f"(c[3])
        : "r"(a[0]), "r"(a[1]), "r"(a[2]), "r"(a[3]), "r"(bq[0]), "r"(bq[1]));
}

// ============================ prep kernels =================================

// kp_w1 (1024,512,3) fp32 -> g_wt [tap][m][c] bf16
__global__ void __launch_bounds__(256) prep_w_kernel(const float* __restrict__ W,
                                                     __nv_bfloat16* __restrict__ Wt)
{
    int idx = blockIdx.x * 256 + threadIdx.x;          // idx = m*512 + c
    if (idx >= 1024 * 512) return;
    const float* s = W + (size_t)idx * 3;
    Wt[(size_t)idx]                    = __float2bfloat16(s[0]);
    Wt[(size_t)(1024 * 512) + idx]     = __float2bfloat16(s[1]);
    Wt[(size_t)(2 * 1024 * 512) + idx] = __float2bfloat16(s[2]);
}

// keys (B,512,200) fp32 -> g_xt [b][t][c] bf16 (tiled transpose)
__global__ void __launch_bounds__(256) prep_x_kernel(const float* __restrict__ X,
                                                     __nv_bfloat16* __restrict__ Xt)
{
    __shared__ float tile[32][33];
    const int b  = blockIdx.z;
    const int t0 = blockIdx.x * 32;
    const int c0 = blockIdx.y * 32;
    const int tx = threadIdx.x, ty = threadIdx.y;
    const float* xb = X + (size_t)b * 512 * T2n;
#pragma unroll
    for (int j = 0; j < 32; j += 8) {
        int c = c0 + ty + j, t = t0 + tx;
        tile[ty + j][tx] = (t < T2n) ? xb[(size_t)c * T2n + t] : 0.f;
    }
    __syncthreads();
    __nv_bfloat16* xo = Xt + (size_t)b * T2n * 512;
#pragma unroll
    for (int j = 0; j < 32; j += 8) {
        int t = t0 + ty + j, c = c0 + tx;
        if (t < T2n) xo[(size_t)t * 512 + c] = __float2bfloat16(tile[tx][ty + j]);
    }
}

// ================= kp_conv1 via bf16 mma.sync (HMMA) =======================
// Y[b,m,t] = relu(bias[m] + sum_{tap,c} W[m,c,tap]*X[b,c,t+tap-1])
// CTA: M=128 x N=64 per batch. 8 warps (4 in M x 2 in N), warp tile 32x32
// (2x4 m16n8k16). K = 24 stages: 3 taps x 8 chunks of 64 channels.
// smem per buf: A 128x64 bf16 (16KB, 128B swizzled rows), B 64x64 (8KB).
// Double buffered via cp.async.

#define KPC_ABUF 16384
#define KPC_BUF  (KPC_ABUF + 8192)       // 24576 per stage buffer
#define KPC_SMEM (2 * KPC_BUF)           // 49152

__global__ void __launch_bounds__(256) kpconv1_mma_kernel(
    const __nv_bfloat16* __restrict__ Wt, const __nv_bfloat16* __restrict__ Xt,
    const float* __restrict__ bias, float* __restrict__ Y)
{
    extern __shared__ char smem[];
    const uint32_t sbase = smem_u32(smem);
    const int tid  = threadIdx.x;
    const int lane = tid & 31;
    const int wid  = tid >> 5;
    const int n0   = blockIdx.x * 64;
    const int m0   = blockIdx.y * 128;
    const int b    = blockIdx.z;

    const int m_off = (wid & 3) * 32;
    const int n_off = (wid >> 2) * 32;

    const __nv_bfloat16* xb = Xt + (size_t)b * (T2n * 512);

    float acc[2][4][4];
#pragma unroll
    for (int mt = 0; mt < 2; mt++)
#pragma unroll
        for (int nt = 0; nt < 4; nt++)
#pragma unroll
            for (int r = 0; r < 4; r++) acc[mt][nt][r] = 0.f;

    // stage fill: tap = s>>3, chunk = s&7
    auto fill = [&](int buf, int s) {
        const int tap = s >> 3, c0 = (s & 7) * 64;
        const uint32_t base = sbase + buf * KPC_BUF;
        // A: 128 rows x 64 ch = 1024 x 16B
#pragma unroll
        for (int k = 0; k < 4; k++) {
            int i = tid + k * 256;
            int row = i >> 3, seg = i & 7;
            const void* src = Wt + ((size_t)tap * 1024 + m0 + row) * 512 + c0 + seg * 8;
            cp16(base + row * 128 + ((seg ^ (row & 7)) * 16), src, 16);
        }
        // B: 64 rows (t = n0+row+tap-1) x 64 ch = 512 x 16B
#pragma unroll
        for (int k = 0; k < 2; k++) {
            int i = tid + k * 256;
            int row = i >> 3, seg = i & 7;
            int t = n0 + row + tap - 1;
            int tc = t < 0 ? 0 : (t >= T2n ? T2n - 1 : t);
            const void* src = xb + (size_t)tc * 512 + c0 + seg * 8;
            int sz = (t >= 0 && t < T2n) ? 16 : 0;
            cp16(base + KPC_ABUF + row * 128 + ((seg ^ (row & 7)) * 16), src, sz);
        }
        CP_COMMIT();
    };

    fill(0, 0);

    const int matm = lane >> 3;          // 0..3 (x4); 0..1 meaningful for x2
    const int lrow = lane & 7;

    for (int s = 0; s < 24; s++) {
        const int cur = s & 1;
        if (s + 1 < 24) {
            fill(cur ^ 1, s + 1);
            asm volatile("cp.async.wait_group 1;" ::: "memory");
        } else {
            asm volatile("cp.async.wait_group 0;" ::: "memory");
        }
        __syncthreads();

        const uint32_t aA = sbase + cur * KPC_BUF;
        const uint32_t aB = aA + KPC_ABUF;
#pragma unroll
        for (int ks = 0; ks < 4; ks++) {
            uint32_t afr[2][4];
#pragma unroll
            for (int mt = 0; mt < 2; mt++) {
                int r = m_off + mt * 16 + (matm & 1) * 8 + lrow;
                int seg = ks * 2 + (matm >> 1);
                ldmx4(afr[mt], aA + r * 128 + ((seg ^ (r & 7)) * 16));
            }
            uint32_t bfr[4][2];
#pragma unroll
            for (int nt = 0; nt < 4; nt++) {
                int r = n_off + nt * 8 + lrow;
                int seg = ks * 2 + (matm & 1);
                ldmx2(bfr[nt], aB + r * 128 + ((seg ^ (r & 7)) * 16));
            }
#pragma unroll
            for (int mt = 0; mt < 2; mt++)
#pragma unroll
                for (int nt = 0; nt < 4; nt++)
                    mma16816(acc[mt][nt], afr[mt], bfr[nt]);
        }
        __syncthreads();
    }

    // epilogue: bias + ReLU
    const int g = lane >> 2, tg = lane & 3;
#pragma unroll
    for (int mt = 0; mt < 2; mt++) {
#pragma unroll
        for (int half = 0; half < 2; half++) {
            const int m = m0 + m_off + mt * 16 + g + half * 8;
            const float bi = bias[m];
            float* yrow = Y + ((size_t)b * 1024 + m) * T2n;
#pragma unroll
            for (int nt = 0; nt < 4; nt++) {
                const int n = n0 + n_off + nt * 8 + tg * 2;
                if (n < T2n) {
                    float2 v;
                    v.x = fmaxf(acc[mt][nt][half * 2 + 0] + bi, 0.f);
                    v.y = fmaxf(acc[mt][nt][half * 2 + 1] + bi, 0.f);
                    *(float2*)(yrow + n) = v;
                }
            }
        }
    }
}

// ====================== SIMT conv-as-GEMM (unchanged) ======================
template <int NTAPS, bool RELU, int TM>
__global__ void __launch_bounds__(128)
conv_gemm_kernel(const float* __restrict__ X, const float* __restrict__ W,
                 const float* __restrict__ bias, float* __restrict__ Y,
                 int M, int N, int Cin)
{
    constexpr int PAD = (NTAPS - 1) / 2;
    constexpr int BM = TM * 8;
    constexpr int BN = 64;
    constexpr int BK = 16;
    constexpr int TN = 4;

    __shared__ float sA[NTAPS][BK][BM];
    __shared__ float sB[BK][BN + 2];

    const int b  = blockIdx.z;
    const int m0 = blockIdx.y * BM;
    const int n0 = blockIdx.x * BN;
    const float* Xb = X + (size_t)b * Cin * N;

    const int tid = threadIdx.x;
    const int tx  = tid & 15;
    const int ty  = tid >> 4;

    float acc[TM][TN];
#pragma unroll
    for (int r = 0; r < TM; r++)
#pragma unroll
        for (int u = 0; u < TN; u++) acc[r][u] = 0.f;

    for (int c0 = 0; c0 < Cin; c0 += BK) {
        for (int idx = tid; idx < BM * BK * NTAPS; idx += 128) {
            int mi  = idx / (BK * NTAPS);
            int r   = idx - mi * (BK * NTAPS);
            int ci  = r / NTAPS;
            int tap = r - ci * NTAPS;
            int m   = m0 + mi;
            float v = (m < M) ? W[((size_t)m * Cin + (c0 + ci)) * NTAPS + tap] : 0.f;
            sA[tap][ci][mi] = v;
        }
        for (int idx = tid; idx < BK * (BN + 2); idx += 128) {
            int ci = idx / (BN + 2);
            int tl = idx - ci * (BN + 2);
            int t  = n0 - PAD + tl;
            float v = (t >= 0 && t < N) ? Xb[(size_t)(c0 + ci) * N + t] : 0.f;
            sB[ci][tl] = v;
        }
        __syncthreads();

#pragma unroll
        for (int kc = 0; kc < BK; kc++) {
            float bv[TN + NTAPS - 1];
#pragma unroll
            for (int u = 0; u < TN + NTAPS - 1; u++) bv[u] = sB[kc][tx * TN + u];
#pragma unroll
            for (int tap = 0; tap < NTAPS; tap++) {
                float av[TM];
#pragma unroll
                for (int r = 0; r < TM; r++) av[r] = sA[tap][kc][ty * TM + r];
#pragma unroll
                for (int r = 0; r < TM; r++)
#pragma unroll
                    for (int u = 0; u < TN; u++)
                        acc[r][u] = fmaf(av[r], bv[u + tap], acc[r][u]);
            }
        }
        __syncthreads();
    }

#pragma unroll
    for (int r = 0; r < TM; r++) {
        int m = m0 + ty * TM + r;
        if (m >= M) break;
        float bi = bias[m];
#pragma unroll
        for (int u = 0; u < TN; u++) {
            int t = n0 + tx * TN + u;
            if (t < N) {
                float v = acc[r][u] + bi;
                if (RELU) v = fmaxf(v, 0.f);
                Y[((size_t)b * M + m) * N + t] = v;
            }
        }
    }
}

// ===================== fused attention (unchanged) =========================
__global__ void __launch_bounds__(256)
attn_kernel(const float* __restrict__ qe, const float* __restrict__ ke,
            const float* __restrict__ prior, const unsigned* __restrict__ mask,
            float* __restrict__ out)
{
    const int b = blockIdx.y;
    const int i = blockIdx.x;
    __shared__ float q[Can];
    __shared__ float red[256];
    const int tid = threadIdx.x;

    if (tid < Can) q[tid] = qe[((size_t)b * Can + tid) * T1n + i];
    __syncthreads();

    const bool valid = tid < T2n;
    float sc = -1e30f;
    if (valid) {
        const float* kp = ke + (size_t)b * Can * T2n + tid;
        float d = 0.f;
#pragma unroll 10
        for (int c = 0; c < Can; c++) {
            float t = q[c] - kp[(size_t)c * T2n];
            d = fmaf(t, t, d);
        }
        sc = -5e-4f * d;
    }

    red[tid] = sc; __syncthreads();
    for (int s = 128; s > 0; s >>= 1) { if (tid < s) red[tid] = fmaxf(red[tid], red[tid + s]); __syncthreads(); }
    float mx = red[0]; __syncthreads();
    red[tid] = valid ? __expf(sc - mx) : 0.f; __syncthreads();
    for (int s = 128; s > 0; s >>= 1) { if (tid < s) red[tid] += red[tid + s]; __syncthreads(); }
    float lse = mx + __logf(red[0]); __syncthreads();

    const size_t base = ((size_t)b * T1n + i) * T2n;
    float lp = 0.f;
    if (valid) {
        lp = sc - lse + __logf(prior[base + tid] + 1e-8f);
        out[(size_t)Bn * T1n * T2n + base + tid] = lp;
    }

    const bool keep = valid && (mask[b * T2n + tid] == 0u);
    float ml = keep ? lp : -1e30f;
    red[tid] = ml; __syncthreads();
    for (int s = 128; s > 0; s >>= 1) { if (tid < s) red[tid] = fmaxf(red[tid], red[tid + s]); __syncthreads(); }
    float m2 = red[0]; __syncthreads();
    red[tid] = keep ? __expf(ml - m2) : 0.f; __syncthreads();
    for (int s = 128; s > 0; s >>= 1) { if (tid < s) red[tid] += red[tid + s]; __syncthreads(); }
    float s2 = red[0];

    if (valid) out[base + tid] = keep ? __expf(ml - m2) / s2 : 0.f;
}

// ---------------------------------------------------------------------------

static void* sym_addr(const void* sym)
{
    void* p = nullptr;
    cudaGetSymbolAddress(&p, sym);
    return p;
}

extern "C" void kernel_launch(void* const* d_in, const int* in_sizes, int n_in,
                              void* d_out, int out_size)
{
    const float*    queries = (const float*)d_in[0];   // (8,80,800)
    const float*    keys    = (const float*)d_in[1];   // (8,512,200)
    const unsigned* mask    = (const unsigned*)d_in[3];// (8,200,1)
    const float*    prior   = (const float*)d_in[4];   // (8,800,200)
    const float*    kp_w1   = (const float*)d_in[5];   // (1024,512,3)
    const float*    kp_b1   = (const float*)d_in[6];
    const float*    kp_w2   = (const float*)d_in[7];   // (80,1024,1)
    const float*    kp_b2   = (const float*)d_in[8];
    const float*    qp_w1   = (const float*)d_in[9];   // (160,80,3)
    const float*    qp_b1   = (const float*)d_in[10];
    const float*    qp_w2   = (const float*)d_in[11];  // (80,160,1)
    const float*    qp_b2   = (const float*)d_in[12];
    const float*    qp_w3   = (const float*)d_in[13];  // (80,80,1)
    const float*    qp_b3   = (const float*)d_in[14];
    float* out = (float*)d_out;

    float* hidK  = (float*)sym_addr(g_hidK);
    float* ke    = (float*)sym_addr(g_ke);
    float* hidQ1 = (float*)sym_addr(g_hidQ1);
    float* hidQ2 = (float*)sym_addr(g_hidQ2);
    float* qe    = (float*)sym_addr(g_qe);
    __nv_bfloat16* wt = (__nv_bfloat16*)sym_addr(g_wt);
    __nv_bfloat16* xt = (__nv_bfloat16*)sym_addr(g_xt);

    // --- key proj stage 1 on mma.sync tensor cores ---
    prep_w_kernel<<<2048, 256>>>(kp_w1, wt);
    prep_x_kernel<<<dim3(7, 16, 8), dim3(32, 8)>>>(keys, xt);
    cudaFuncSetAttribute(kpconv1_mma_kernel,
                         cudaFuncAttributeMaxDynamicSharedMemorySize, KPC_SMEM);
    kpconv1_mma_kernel<<<dim3(4, 8, 8), 256, KPC_SMEM>>>(wt, xt, kp_b1, hidK);

    // key proj stage 2 (SIMT)
    conv_gemm_kernel<1, false, 4><<<dim3(4, 3, 8), 128>>>(hidK, kp_w2, kp_b2, ke, 80, 200, 1024);

    // query proj chain (SIMT)
    conv_gemm_kernel<3, true, 4><<<dim3(13, 5, 8), 128>>>(queries, qp_w1, qp_b1, hidQ1, 160, 800, 80);
    conv_gemm_kernel<1, true, 4><<<dim3(13, 3, 8), 128>>>(hidQ1, qp_w2, qp_b2, hidQ2, 80, 800, 160);
    conv_gemm_kernel<1, false, 4><<<dim3(13, 3, 8), 128>>>(hidQ2, qp_w3, qp_b3, qe, 80, 800, 80);

    // fused distance + log_softmax + prior + masked softmax
    attn_kernel<<<dim3(T1n, Bn), 256>>>(qe, ke, prior, mask, out);
}

// round 6
// speedup vs baseline: 5.1780x; 2.6389x over previous
#include <cuda_runtime.h>
#include <cuda_bf16.h>
#include <cstdint>

// ---------------------------------------------------------------------------
// ConvAttention, R5: every GEMM-shaped stage on bf16 mma.sync (HMMA).
//   kp_conv1 (512->1024,k3)      : kpconv1_mma (M=out-ch axis)   -> bf16 [t][1024]
//   kp_conv2 (1024->80,k1)       : convmma (time-major)          -> bf16 [t][128]
//   qp chain (80->160->80->80)   : convmma x3                    -> bf16 [t][128]
//   q.k Gram matrix              : convmma (ke acts as weights)  -> fp32 G[i][j]
//   softmax stage                : streaming kernel over G + norms + prior + mask
// ---------------------------------------------------------------------------

#define Bn   8
#define T1n  800
#define T2n  200

// -------- scratch (device globals; no allocation allowed) --------
__device__ __nv_bfloat16 g_xt [8 * 200 * 512];    // keys   [b][t][512]
__device__ __nv_bfloat16 g_xq [8 * 800 * 128];    // queries[b][t][128] (80 pad)
__device__ __nv_bfloat16 g_h1 [8 * 200 * 1024];   // key conv1 out [b][t][1024]
__device__ __nv_bfloat16 g_keb[8 * 200 * 128];    // key emb  [b][t][128] (80 pad)
__device__ __nv_bfloat16 g_hq1[8 * 800 * 192];    // qp1 out  [b][t][192] (160 pad)
__device__ __nv_bfloat16 g_hq2[8 * 800 * 128];    // qp2 out
__device__ __nv_bfloat16 g_qeb[8 * 800 * 128];    // query emb
__device__ __nv_bfloat16 g_wt [3 * 1024 * 512];   // kp_w1 [tap][m][512]
__device__ __nv_bfloat16 g_wk2[80 * 1024];        // kp_w2 [m][1024]
__device__ __nv_bfloat16 g_wq1[3 * 160 * 128];    // qp_w1 [tap][m][128]
__device__ __nv_bfloat16 g_wq2[80 * 192];
__device__ __nv_bfloat16 g_wq3[80 * 128];
__device__ float g_G  [8 * 800 * 200];            // q.k
__device__ float g_nq [8 * 800];
__device__ float g_nk [8 * 200];
__device__ float g_zbias[256];                    // zero-init, never written

// ========================= inline PTX helpers ==============================

__device__ __forceinline__ uint32_t smem_u32(const void* p) {
    uint32_t a;
    asm("{ .reg .u64 t; cvta.to.shared.u64 t, %1; cvt.u32.u64 %0, t; }"
        : "=r"(a) : "l"(p));
    return a;
}
__device__ __forceinline__ void cp16(uint32_t dst, const void* src, int sz) {
    asm volatile("cp.async.cg.shared.global [%0], [%1], 16, %2;"
                 :: "r"(dst), "l"(src), "r"(sz) : "memory");
}
#define CP_COMMIT() asm volatile("cp.async.commit_group;" ::: "memory")

__device__ __forceinline__ void ldmx4(uint32_t* r, uint32_t addr) {
    asm volatile("ldmatrix.sync.aligned.m8n8.x4.shared.b16 {%0,%1,%2,%3}, [%4];"
                 : "=r"(r[0]), "=r"(r[1]), "=r"(r[2]), "=r"(r[3]) : "r"(addr));
}
__device__ __forceinline__ void ldmx2(uint32_t* r, uint32_t addr) {
    asm volatile("ldmatrix.sync.aligned.m8n8.x2.shared.b16 {%0,%1}, [%2];"
                 : "=r"(r[0]), "=r"(r[1]) : "r"(addr));
}
__device__ __forceinline__ void mma16816(float* c, const uint32_t* a, const uint32_t* bq) {
    asm volatile(
        "mma.sync.aligned.m16n8k16.row.col.f32.bf16.bf16.f32 "
        "{%0,%1,%2,%3}, {%4,%5,%6,%7}, {%8,%9}, {%0,%1,%2,%3};"
        : "+f"(c[0]), "+f"(c[1]), "+f"(c[2]), "+f"(c[3])
        : "r"(a[0]), "r"(a[1]), "r"(a[2]), "r"(a[3]), "r"(bq[0]), "r"(bq[1]));
}

// ============================ prep kernels =================================

// kp_w1 (1024,512,3) fp32 -> g_wt [tap][m][c] bf16
__global__ void __launch_bounds__(256) prep_w_kernel(const float* __restrict__ W,
                                                     __nv_bfloat16* __restrict__ Wt)
{
    int idx = blockIdx.x * 256 + threadIdx.x;
    if (idx >= 1024 * 512) return;
    const float* s = W + (size_t)idx * 3;
    Wt[(size_t)idx]                    = __float2bfloat16(s[0]);
    Wt[(size_t)(1024 * 512) + idx]     = __float2bfloat16(s[1]);
    Wt[(size_t)(2 * 1024 * 512) + idx] = __float2bfloat16(s[2]);
}

// generic weight prep: W (M, Cin, taps) fp32 -> [tap][m][Cpad] bf16 (zero pad)
__global__ void __launch_bounds__(256) prep_wgen_kernel(const float* __restrict__ W,
                                                        __nv_bfloat16* __restrict__ Wt,
                                                        int M, int Cin, int Cpad, int taps)
{
    int idx = blockIdx.x * 256 + threadIdx.x;
    int total = taps * M * Cpad;
    if (idx >= total) return;
    int c = idx % Cpad;
    int r = idx / Cpad;
    int m = r % M;
    int tap = r / M;
    float v = (c < Cin) ? W[((size_t)m * Cin + c) * taps + tap] : 0.f;
    Wt[idx] = __float2bfloat16(v);
}

// X (B, C, T) fp32 -> [b][t][Cpad] bf16 transpose (zero pad)
__global__ void __launch_bounds__(256) prep_xpose_kernel(const float* __restrict__ X,
                                                         __nv_bfloat16* __restrict__ Xt,
                                                         int C, int T, int Cpad)
{
    __shared__ float tile[32][33];
    const int b  = blockIdx.z;
    const int t0 = blockIdx.x * 32;
    const int c0 = blockIdx.y * 32;
    const int tx = threadIdx.x, ty = threadIdx.y;
    const float* xb = X + (size_t)b * C * T;
#pragma unroll
    for (int j = 0; j < 32; j += 8) {
        int c = c0 + ty + j, t = t0 + tx;
        tile[ty + j][tx] = (c < C && t < T) ? xb[(size_t)c * T + t] : 0.f;
    }
    __syncthreads();
    __nv_bfloat16* xo = Xt + (size_t)b * T * Cpad;
#pragma unroll
    for (int j = 0; j < 32; j += 8) {
        int t = t0 + ty + j, c = c0 + tx;
        if (t < T && c < Cpad) xo[(size_t)t * Cpad + c] = __float2bfloat16(tile[tx][ty + j]);
    }
}

// zero pad cols [80,128) of ke_bf (so G pad contributions vanish)
__global__ void __launch_bounds__(256) zero_kepad_kernel(__nv_bfloat16* __restrict__ ke)
{
    int idx = blockIdx.x * 256 + threadIdx.x;     // 1600 rows * 48 cols
    if (idx >= 8 * 200 * 48) return;
    int row = idx / 48, c = idx % 48;
    ke[(size_t)row * 128 + 80 + c] = __float2bfloat16(0.f);
}

// row norms: out[r] = sum_{c<80} E[r][c]^2   (E rows are [.][128] bf16)
__global__ void __launch_bounds__(256) norms_kernel(const __nv_bfloat16* __restrict__ E,
                                                    float* __restrict__ out, int rows)
{
    int r = blockIdx.x * 256 + threadIdx.x;
    if (r >= rows) return;
    const __nv_bfloat162* p = (const __nv_bfloat162*)(E + (size_t)r * 128);
    float s = 0.f;
#pragma unroll
    for (int c = 0; c < 40; c++) {
        float2 v = __bfloat1622float2(p[c]);
        s = fmaf(v.x, v.x, fmaf(v.y, v.y, s));
    }
    out[r] = s;
}

// ================= kp_conv1 via bf16 mma.sync (out-ch major) ===============
// CTA: M=128 (out-ch) x N=64 (t). 24 stages: 3 taps x 8 chunks of 64 channels.
// Epilogue: smem-staged transpose -> bf16 hidK [b][t][1024].

#define KPC_ABUF 16384
#define KPC_BUF  (KPC_ABUF + 8192)
#define KPC_SMEM (2 * KPC_BUF)

__global__ void __launch_bounds__(256) kpconv1_mma_kernel(
    const __nv_bfloat16* __restrict__ Wt, const __nv_bfloat16* __restrict__ Xt,
    const float* __restrict__ bias, __nv_bfloat16* __restrict__ Y)
{
    extern __shared__ char smem[];
    const uint32_t sbase = smem_u32(smem);
    const int tid  = threadIdx.x;
    const int lane = tid & 31;
    const int wid  = tid >> 5;
    const int n0   = blockIdx.x * 64;
    const int m0   = blockIdx.y * 128;
    const int b    = blockIdx.z;

    const int m_off = (wid & 3) * 32;
    const int n_off = (wid >> 2) * 32;

    const __nv_bfloat16* xb = Xt + (size_t)b * (T2n * 512);

    float acc[2][4][4];
#pragma unroll
    for (int mt = 0; mt < 2; mt++)
#pragma unroll
        for (int nt = 0; nt < 4; nt++)
#pragma unroll
            for (int r = 0; r < 4; r++) acc[mt][nt][r] = 0.f;

    auto fill = [&](int buf, int s) {
        const int tap = s >> 3, c0 = (s & 7) * 64;
        const uint32_t base = sbase + buf * KPC_BUF;
#pragma unroll
        for (int k = 0; k < 4; k++) {
            int i = tid + k * 256;
            int row = i >> 3, seg = i & 7;
            const void* src = Wt + ((size_t)tap * 1024 + m0 + row) * 512 + c0 + seg * 8;
            cp16(base + row * 128 + ((seg ^ (row & 7)) * 16), src, 16);
        }
#pragma unroll
        for (int k = 0; k < 2; k++) {
            int i = tid + k * 256;
            int row = i >> 3, seg = i & 7;
            int t = n0 + row + tap - 1;
            int tc = t < 0 ? 0 : (t >= T2n ? T2n - 1 : t);
            const void* src = xb + (size_t)tc * 512 + c0 + seg * 8;
            int sz = (t >= 0 && t < T2n) ? 16 : 0;
            cp16(base + KPC_ABUF + row * 128 + ((seg ^ (row & 7)) * 16), src, sz);
        }
        CP_COMMIT();
    };

    fill(0, 0);
    const int matm = lane >> 3;
    const int lrow = lane & 7;

    for (int s = 0; s < 24; s++) {
        const int cur = s & 1;
        if (s + 1 < 24) {
            fill(cur ^ 1, s + 1);
            asm volatile("cp.async.wait_group 1;" ::: "memory");
        } else {
            asm volatile("cp.async.wait_group 0;" ::: "memory");
        }
        __syncthreads();

        const uint32_t aA = sbase + cur * KPC_BUF;
        const uint32_t aB = aA + KPC_ABUF;
#pragma unroll
        for (int ks = 0; ks < 4; ks++) {
            uint32_t afr[2][4];
#pragma unroll
            for (int mt = 0; mt < 2; mt++) {
                int r = m_off + mt * 16 + (matm & 1) * 8 + lrow;
                int seg = ks * 2 + (matm >> 1);
                ldmx4(afr[mt], aA + r * 128 + ((seg ^ (r & 7)) * 16));
            }
            uint32_t bfr[4][2];
#pragma unroll
            for (int nt = 0; nt < 4; nt++) {
                int r = n_off + nt * 8 + lrow;
                int seg = ks * 2 + (matm & 1);
                ldmx2(bfr[nt], aB + r * 128 + ((seg ^ (r & 7)) * 16));
            }
#pragma unroll
            for (int mt = 0; mt < 2; mt++)
#pragma unroll
                for (int nt = 0; nt < 4; nt++)
                    mma16816(acc[mt][nt], afr[mt], bfr[nt]);
        }
        __syncthreads();
    }

    // epilogue: bias+ReLU, stage [64 t][128 m] bf16 tile in smem, store [t][1024]
    __nv_bfloat16* sE = (__nv_bfloat16*)smem;
    const int g = lane >> 2, tg = lane & 3;
#pragma unroll
    for (int mt = 0; mt < 2; mt++) {
#pragma unroll
        for (int half = 0; half < 2; half++) {
            const int ml = m_off + mt * 16 + g + half * 8;
            const float bi = bias[m0 + ml];
#pragma unroll
            for (int nt = 0; nt < 4; nt++) {
                const int tl = n_off + nt * 8 + tg * 2;
                sE[(size_t)tl * 128 + ml] =
                    __float2bfloat16(fmaxf(acc[mt][nt][half * 2 + 0] + bi, 0.f));
                sE[(size_t)(tl + 1) * 128 + ml] =
                    __float2bfloat16(fmaxf(acc[mt][nt][half * 2 + 1] + bi, 0.f));
            }
        }
    }
    __syncthreads();
    const uint4* sv = (const uint4*)sE;
#pragma unroll
    for (int k = 0; k < 4; k++) {
        int i = tid + k * 256;                    // 1024 uint4 (64 rows x 16)
        int row = i >> 4, seg = i & 15;
        int t = n0 + row;
        if (t < T2n)
            *(uint4*)(Y + ((size_t)b * T2n + t) * 1024 + m0 + seg * 8) = sv[i];
    }
}

// ================= generic time-major conv/GEMM on mma.sync ================
// Y[b][t][m] = act( bias[m] + sum_{tap,c} W[(b)][tap][m][c] * X[b][t+tap-PAD][c] )
// CTA tile: 128 t x 80 m. 8 warps = 4(t) x 2(m); warp 32t x 40m (2x5 m16n8k16).
// OUT=0: bf16 [t][ystride];  OUT=1: fp32 [t][ystride].

template <int TAPS, bool RELU, int OUT>
__global__ void __launch_bounds__(256) convmma_kernel(
    const __nv_bfloat16* __restrict__ X, const __nv_bfloat16* __restrict__ W,
    const float* __restrict__ bias, void* __restrict__ Yv,
    int N_t, int Mtot, int Cpad, int nChunks, int wbstride, int ystride)
{
    constexpr int PAD   = (TAPS - 1) / 2;
    constexpr int AROWS = 128 + TAPS - 1;
    constexpr int ABUF  = AROWS * 128;
    constexpr int BROWS = TAPS * 80;
    constexpr int BBUF  = BROWS * 128;
    constexpr int BUF   = ABUF + BBUF;

    extern __shared__ char smem[];
    const uint32_t sbase = smem_u32(smem);
    const int tid  = threadIdx.x;
    const int lane = tid & 31;
    const int wid  = tid >> 5;
    const int t0   = blockIdx.x * 128;
    const int m0   = blockIdx.y * 80;
    const int b    = blockIdx.z;

    const int t_off = (wid & 3) * 32;
    const int m_off = (wid >> 2) * 40;

    const __nv_bfloat16* xb = X + (size_t)b * N_t * Cpad;
    const __nv_bfloat16* wb = W + (size_t)b * wbstride;

    float acc[2][5][4];
#pragma unroll
    for (int mt = 0; mt < 2; mt++)
#pragma unroll
        for (int nt = 0; nt < 5; nt++)
#pragma unroll
            for (int r = 0; r < 4; r++) acc[mt][nt][r] = 0.f;

    auto fill = [&](int buf, int chunk) {
        const int c0 = chunk * 64;
        const uint32_t base = sbase + buf * BUF;
        for (int i = tid; i < AROWS * 8; i += 256) {
            int row = i >> 3, seg = i & 7;
            int t = t0 + row - PAD;
            int tc = t < 0 ? 0 : (t >= N_t ? N_t - 1 : t);
            const void* src = xb + (size_t)tc * Cpad + c0 + seg * 8;
            int sz = (t >= 0 && t < N_t) ? 16 : 0;
            cp16(base + row * 128 + ((seg ^ (row & 7)) * 16), src, sz);
        }
        for (int i = tid; i < BROWS * 8; i += 256) {
            int row = i >> 3, seg = i & 7;
            int tap = row / 80;
            int m = m0 + (row - tap * 80);
            int mc = m < Mtot ? m : Mtot - 1;
            const void* src = wb + ((size_t)tap * Mtot + mc) * Cpad + c0 + seg * 8;
            int sz = (m < Mtot) ? 16 : 0;
            cp16(base + ABUF + row * 128 + ((seg ^ (row & 7)) * 16), src, sz);
        }
        CP_COMMIT();
    };

    fill(0, 0);
    const int matm = lane >> 3;
    const int lrow = lane & 7;

    for (int s = 0; s < nChunks; s++) {
        const int cur = s & 1;
        if (s + 1 < nChunks) {
            fill(cur ^ 1, s + 1);
            asm volatile("cp.async.wait_group 1;" ::: "memory");
        } else {
            asm volatile("cp.async.wait_group 0;" ::: "memory");
        }
        __syncthreads();

        const uint32_t aA = sbase + cur * BUF;
        const uint32_t aB = aA + ABUF;
#pragma unroll
        for (int tap = 0; tap < TAPS; tap++) {
#pragma unroll
            for (int ks = 0; ks < 4; ks++) {
                uint32_t afr[2][4];
#pragma unroll
                for (int mt = 0; mt < 2; mt++) {
                    int r = t_off + mt * 16 + (matm & 1) * 8 + lrow + tap;
                    int seg = ks * 2 + (matm >> 1);
                    ldmx4(afr[mt], aA + r * 128 + ((seg ^ (r & 7)) * 16));
                }
                uint32_t bfr[5][2];
#pragma unroll
                for (int nt = 0; nt < 5; nt++) {
                    int r = tap * 80 + m_off + nt * 8 + lrow;
                    int seg = ks * 2 + (matm & 1);
                    ldmx2(bfr[nt], aB + r * 128 + ((seg ^ (r & 7)) * 16));
                }
#pragma unroll
                for (int mt = 0; mt < 2; mt++)
#pragma unroll
                    for (int nt = 0; nt < 5; nt++)
                        mma16816(acc[mt][nt], afr[mt], bfr[nt]);
            }
        }
        __syncthreads();
    }

    // epilogue: rows = time, cols = out-channels
    const int g = lane >> 2, tg = lane & 3;
#pragma unroll
    for (int mt = 0; mt < 2; mt++) {
#pragma unroll
        for (int half = 0; half < 2; half++) {
            const int t = t0 + t_off + mt * 16 + g + half * 8;
            if (t >= N_t) continue;
#pragma unroll
            for (int nt = 0; nt < 5; nt++) {
                const int m = m0 + m_off + nt * 8 + tg * 2;
                if (m >= Mtot) continue;
                float v0 = acc[mt][nt][half * 2 + 0] + bias[m];
                float v1 = acc[mt][nt][half * 2 + 1] + bias[m + 1];
                if (RELU) { v0 = fmaxf(v0, 0.f); v1 = fmaxf(v1, 0.f); }
                if (OUT == 0) {
                    __nv_bfloat162* y = (__nv_bfloat162*)
                        ((__nv_bfloat16*)Yv + ((size_t)b * N_t + t) * ystride + m);
                    *y = __floats2bfloat162_rn(v0, v1);
                } else {
                    float2* y = (float2*)
                        ((float*)Yv + ((size_t)b * N_t + t) * ystride + m);
                    *y = make_float2(v0, v1);
                }
            }
        }
    }
}

// ===================== softmax stage (streaming) ===========================
// sc[j] = -5e-4*(nq[i] + nk[j] - 2*G[b][i][j]); then log_softmax + prior,
// then masked softmax. One block per (b, i).
__global__ void __launch_bounds__(256)
attn2_kernel(const float* __restrict__ G, const float* __restrict__ nq,
             const float* __restrict__ nk, const float* __restrict__ prior,
             const unsigned* __restrict__ mask, float* __restrict__ out)
{
    const int b = blockIdx.y;
    const int i = blockIdx.x;
    __shared__ float red[256];
    const int tid = threadIdx.x;

    const bool valid = tid < T2n;
    float sc = -1e30f;
    if (valid) {
        float d = nq[b * T1n + i] + nk[b * T2n + tid]
                - 2.f * G[((size_t)b * T1n + i) * T2n + tid];
        sc = -5e-4f * d;
    }

    red[tid] = sc; __syncthreads();
    for (int s = 128; s > 0; s >>= 1) { if (tid < s) red[tid] = fmaxf(red[tid], red[tid + s]); __syncthreads(); }
    float mx = red[0]; __syncthreads();
    red[tid] = valid ? __expf(sc - mx) : 0.f; __syncthreads();
    for (int s = 128; s > 0; s >>= 1) { if (tid < s) red[tid] += red[tid + s]; __syncthreads(); }
    float lse = mx + __logf(red[0]); __syncthreads();

    const size_t base = ((size_t)b * T1n + i) * T2n;
    float lp = 0.f;
    if (valid) {
        lp = sc - lse + __logf(prior[base + tid] + 1e-8f);
        out[(size_t)Bn * T1n * T2n + base + tid] = lp;
    }

    const bool keep = valid && (mask[b * T2n + tid] == 0u);
    float ml = keep ? lp : -1e30f;
    red[tid] = ml; __syncthreads();
    for (int s = 128; s > 0; s >>= 1) { if (tid < s) red[tid] = fmaxf(red[tid], red[tid + s]); __syncthreads(); }
    float m2 = red[0]; __syncthreads();
    red[tid] = keep ? __expf(ml - m2) : 0.f; __syncthreads();
    for (int s = 128; s > 0; s >>= 1) { if (tid < s) red[tid] += red[tid + s]; __syncthreads(); }
    float s2 = red[0];

    if (valid) out[base + tid] = keep ? __expf(ml - m2) / s2 : 0.f;
}

// ---------------------------------------------------------------------------

static void* sym_addr(const void* sym)
{
    void* p = nullptr;
    cudaGetSymbolAddress(&p, sym);
    return p;
}

extern "C" void kernel_launch(void* const* d_in, const int* in_sizes, int n_in,
                              void* d_out, int out_size)
{
    const float*    queries = (const float*)d_in[0];   // (8,80,800)
    const float*    keys    = (const float*)d_in[1];   // (8,512,200)
    const unsigned* mask    = (const unsigned*)d_in[3];// (8,200,1)
    const float*    prior   = (const float*)d_in[4];   // (8,800,200)
    const float*    kp_w1   = (const float*)d_in[5];
    const float*    kp_b1   = (const float*)d_in[6];
    const float*    kp_w2   = (const float*)d_in[7];
    const float*    kp_b2   = (const float*)d_in[8];
    const float*    qp_w1   = (const float*)d_in[9];
    const float*    qp_b1   = (const float*)d_in[10];
    const float*    qp_w2   = (const float*)d_in[11];
    const float*    qp_b2   = (const float*)d_in[12];
    const float*    qp_w3   = (const float*)d_in[13];
    const float*    qp_b3   = (const float*)d_in[14];
    float* out = (float*)d_out;

    __nv_bfloat16* xt  = (__nv_bfloat16*)sym_addr(g_xt);
    __nv_bfloat16* xq  = (__nv_bfloat16*)sym_addr(g_xq);
    __nv_bfloat16* h1  = (__nv_bfloat16*)sym_addr(g_h1);
    __nv_bfloat16* keb = (__nv_bfloat16*)sym_addr(g_keb);
    __nv_bfloat16* hq1 = (__nv_bfloat16*)sym_addr(g_hq1);
    __nv_bfloat16* hq2 = (__nv_bfloat16*)sym_addr(g_hq2);
    __nv_bfloat16* qeb = (__nv_bfloat16*)sym_addr(g_qeb);
    __nv_bfloat16* wt  = (__nv_bfloat16*)sym_addr(g_wt);
    __nv_bfloat16* wk2 = (__nv_bfloat16*)sym_addr(g_wk2);
    __nv_bfloat16* wq1 = (__nv_bfloat16*)sym_addr(g_wq1);
    __nv_bfloat16* wq2 = (__nv_bfloat16*)sym_addr(g_wq2);
    __nv_bfloat16* wq3 = (__nv_bfloat16*)sym_addr(g_wq3);
    float* G   = (float*)sym_addr(g_G);
    float* nq  = (float*)sym_addr(g_nq);
    float* nk  = (float*)sym_addr(g_nk);
    float* zb  = (float*)sym_addr(g_zbias);

    static bool attr_set = false;
    if (!attr_set) {
        cudaFuncSetAttribute(kpconv1_mma_kernel,
                             cudaFuncAttributeMaxDynamicSharedMemorySize, KPC_SMEM);
        cudaFuncSetAttribute(convmma_kernel<1, false, 0>,
                             cudaFuncAttributeMaxDynamicSharedMemorySize, 2 * (128 + 80) * 128);
        cudaFuncSetAttribute(convmma_kernel<1, true, 0>,
                             cudaFuncAttributeMaxDynamicSharedMemorySize, 2 * (128 + 80) * 128);
        cudaFuncSetAttribute(convmma_kernel<1, false, 1>,
                             cudaFuncAttributeMaxDynamicSharedMemorySize, 2 * (128 + 80) * 128);
        cudaFuncSetAttribute(convmma_kernel<3, true, 0>,
                             cudaFuncAttributeMaxDynamicSharedMemorySize, 2 * (130 + 240) * 128);
        attr_set = true;
    }

    // ---- preps ----
    prep_w_kernel<<<2048, 256>>>(kp_w1, wt);
    prep_xpose_kernel<<<dim3(7, 16, 8), dim3(32, 8)>>>(keys, xt, 512, T2n, 512);
    prep_xpose_kernel<<<dim3(25, 4, 8), dim3(32, 8)>>>(queries, xq, 80, T1n, 128);
    prep_wgen_kernel<<<(80 * 1024 + 255) / 256, 256>>>(kp_w2, wk2, 80, 1024, 1024, 1);
    prep_wgen_kernel<<<(3 * 160 * 128 + 255) / 256, 256>>>(qp_w1, wq1, 160, 80, 128, 3);
    prep_wgen_kernel<<<(80 * 192 + 255) / 256, 256>>>(qp_w2, wq2, 80, 160, 192, 1);
    prep_wgen_kernel<<<(80 * 128 + 255) / 256, 256>>>(qp_w3, wq3, 80, 80, 128, 1);

    // ---- key projection ----
    kpconv1_mma_kernel<<<dim3(4, 8, 8), 256, KPC_SMEM>>>(wt, xt, kp_b1, h1);
    convmma_kernel<1, false, 0><<<dim3(2, 1, 8), 256, 2 * (128 + 80) * 128>>>(
        h1, wk2, kp_b2, keb, T2n, 80, 1024, 16, 0, 128);
    zero_kepad_kernel<<<(8 * 200 * 48 + 255) / 256, 256>>>(keb);

    // ---- query projection chain ----
    convmma_kernel<3, true, 0><<<dim3(7, 2, 8), 256, 2 * (130 + 240) * 128>>>(
        xq, wq1, qp_b1, hq1, T1n, 160, 128, 2, 0, 192);
    convmma_kernel<1, true, 0><<<dim3(7, 1, 8), 256, 2 * (128 + 80) * 128>>>(
        hq1, wq2, qp_b2, hq2, T1n, 80, 192, 3, 0, 128);
    convmma_kernel<1, false, 0><<<dim3(7, 1, 8), 256, 2 * (128 + 80) * 128>>>(
        hq2, wq3, qp_b3, qeb, T1n, 80, 128, 2, 0, 128);

    // ---- Gram matrix G = qe . ke^T  (ke acts as batched "weights") ----
    convmma_kernel<1, false, 1><<<dim3(7, 3, 8), 256, 2 * (128 + 80) * 128>>>(
        qeb, keb, zb, G, T1n, T2n, 128, 2, T2n * 128, T2n);

    // ---- norms + softmax stage ----
    norms_kernel<<<(8 * T1n + 255) / 256, 256>>>(qeb, nq, 8 * T1n);
    norms_kernel<<<(8 * T2n + 255) / 256, 256>>>(keb, nk, 8 * T2n);
    attn2_kernel<<<dim3(T1n, Bn), 256>>>(G, nq, nk, prior, mask, out);
}

// round 7
// speedup vs baseline: 7.3723x; 1.4238x over previous
#include <cuda_runtime.h>
#include <cuda_bf16.h>
#include <cstdint>

// ---------------------------------------------------------------------------
// ConvAttention, R6: all GEMM stages through one generic time-major bf16
// mma.sync conv/GEMM kernel; split-K for kp2; warp-per-row softmax stage.
// ---------------------------------------------------------------------------

#define Bn   8
#define T1n  800
#define T2n  200

// -------- scratch (device globals; zero-initialized at module load) --------
__device__ __nv_bfloat16 g_xt [8 * 200 * 512];    // keys   [b][t][512]
__device__ __nv_bfloat16 g_xq [8 * 800 * 128];    // queries[b][t][128] (80 pad)
__device__ __nv_bfloat16 g_h1 [8 * 200 * 1024];   // key conv1 out [b][t][1024]
__device__ __nv_bfloat16 g_keb[8 * 200 * 128];    // key emb  [b][t][128] (80 pad, pads stay 0)
__device__ __nv_bfloat16 g_hq1[8 * 800 * 192];    // qp1 out  [b][t][192]
__device__ __nv_bfloat16 g_hq2[8 * 800 * 128];    // qp2 out
__device__ __nv_bfloat16 g_qeb[8 * 800 * 128];    // query emb
__device__ __nv_bfloat16 g_wt [3 * 1024 * 512];   // kp_w1 [tap][m][512]
__device__ __nv_bfloat16 g_wk2[80 * 1024];
__device__ __nv_bfloat16 g_wq1[3 * 160 * 128];
__device__ __nv_bfloat16 g_wq2[80 * 192];
__device__ __nv_bfloat16 g_wq3[80 * 128];
__device__ float g_part[4 * 1600 * 80];           // kp2 split-K partials
__device__ float g_G  [8 * 800 * 200];            // q.k
__device__ float g_nk [8 * 200];
__device__ float g_zbias[256];                    // zeros

// ========================= inline PTX helpers ==============================

__device__ __forceinline__ uint32_t smem_u32(const void* p) {
    uint32_t a;
    asm("{ .reg .u64 t; cvta.to.shared.u64 t, %1; cvt.u32.u64 %0, t; }"
        : "=r"(a) : "l"(p));
    return a;
}
__device__ __forceinline__ void cp16(uint32_t dst, const void* src, int sz) {
    asm volatile("cp.async.cg.shared.global [%0], [%1], 16, %2;"
                 :: "r"(dst), "l"(src), "r"(sz) : "memory");
}
#define CP_COMMIT() asm volatile("cp.async.commit_group;" ::: "memory")

__device__ __forceinline__ void ldmx4(uint32_t* r, uint32_t addr) {
    asm volatile("ldmatrix.sync.aligned.m8n8.x4.shared.b16 {%0,%1,%2,%3}, [%4];"
                 : "=r"(r[0]), "=r"(r[1]), "=r"(r[2]), "=r"(r[3]) : "r"(addr));
}
__device__ __forceinline__ void ldmx2(uint32_t* r, uint32_t addr) {
    asm volatile("ldmatrix.sync.aligned.m8n8.x2.shared.b16 {%0,%1}, [%2];"
                 : "=r"(r[0]), "=r"(r[1]) : "r"(addr));
}
__device__ __forceinline__ void mma16816(float* c, const uint32_t* a, const uint32_t* bq) {
    asm volatile(
        "mma.sync.aligned.m16n8k16.row.col.f32.bf16.bf16.f32 "
        "{%0,%1,%2,%3}, {%4,%5,%6,%7}, {%8,%9}, {%0,%1,%2,%3};"
        : "+f"(c[0]), "+f"(c[1]), "+f"(c[2]), "+f"(c[3])
        : "r"(a[0]), "r"(a[1]), "r"(a[2]), "r"(a[3]), "r"(bq[0]), "r"(bq[1]));
}

// ============================ prep kernels =================================

__device__ __forceinline__ void wprep_one(const float* W, __nv_bfloat16* Wt,
                                          int idx, int M, int Cin, int Cpad, int taps)
{
    int c = idx % Cpad;
    int r = idx / Cpad;
    int m = r % M;
    int tap = r / M;
    float v = (c < Cin) ? W[((size_t)m * Cin + c) * taps + tap] : 0.f;
    Wt[idx] = __float2bfloat16(v);
}

// all five weight tensors in one launch
#define WP0 (3 * 1024 * 512)
#define WP1 (80 * 1024)
#define WP2 (3 * 160 * 128)
#define WP3 (80 * 192)
#define WP4 (80 * 128)
__global__ void __launch_bounds__(256) prep_weights_kernel(
    const float* __restrict__ w1, const float* __restrict__ w2,
    const float* __restrict__ q1, const float* __restrict__ q2,
    const float* __restrict__ q3,
    __nv_bfloat16* __restrict__ o1, __nv_bfloat16* __restrict__ o2,
    __nv_bfloat16* __restrict__ o3, __nv_bfloat16* __restrict__ o4,
    __nv_bfloat16* __restrict__ o5)
{
    int idx = blockIdx.x * 256 + threadIdx.x;
    if (idx < WP0) { wprep_one(w1, o1, idx, 1024, 512, 512, 3); return; }
    idx -= WP0;
    if (idx < WP1) { wprep_one(w2, o2, idx, 80, 1024, 1024, 1); return; }
    idx -= WP1;
    if (idx < WP2) { wprep_one(q1, o3, idx, 160, 80, 128, 3); return; }
    idx -= WP2;
    if (idx < WP3) { wprep_one(q2, o4, idx, 80, 160, 192, 1); return; }
    idx -= WP3;
    if (idx < WP4) { wprep_one(q3, o5, idx, 80, 80, 128, 1); }
}

// X (B, C, T) fp32 -> [b][t][Cpad] bf16 transpose (zero pad)
__global__ void __launch_bounds__(256) prep_xpose_kernel(const float* __restrict__ X,
                                                         __nv_bfloat16* __restrict__ Xt,
                                                         int C, int T, int Cpad)
{
    __shared__ float tile[32][33];
    const int b  = blockIdx.z;
    const int t0 = blockIdx.x * 32;
    const int c0 = blockIdx.y * 32;
    const int tx = threadIdx.x, ty = threadIdx.y;
    const float* xb = X + (size_t)b * C * T;
#pragma unroll
    for (int j = 0; j < 32; j += 8) {
        int c = c0 + ty + j, t = t0 + tx;
        tile[ty + j][tx] = (c < C && t < T) ? xb[(size_t)c * T + t] : 0.f;
    }
    __syncthreads();
    __nv_bfloat16* xo = Xt + (size_t)b * T * Cpad;
#pragma unroll
    for (int j = 0; j < 32; j += 8) {
        int t = t0 + ty + j, c = c0 + tx;
        if (t < T && c < Cpad) xo[(size_t)t * Cpad + c] = __float2bfloat16(tile[tx][ty + j]);
    }
}

// nk row norms: out[r] = sum_{c<80} E[r][c]^2
__global__ void __launch_bounds__(256) norms_kernel(const __nv_bfloat16* __restrict__ E,
                                                    float* __restrict__ out, int rows)
{
    int r = blockIdx.x * 256 + threadIdx.x;
    if (r >= rows) return;
    const __nv_bfloat162* p = (const __nv_bfloat162*)(E + (size_t)r * 128);
    float s = 0.f;
#pragma unroll
    for (int c = 0; c < 40; c++) {
        float2 v = __bfloat1622float2(p[c]);
        s = fmaf(v.x, v.x, fmaf(v.y, v.y, s));
    }
    out[r] = s;
}

// kp2 split-K reduce: keb[row][m] = bf16(sum_slices part + bias[m])
__global__ void __launch_bounds__(256) reduce_kp2_kernel(const float* __restrict__ part,
                                                         const float* __restrict__ bias,
                                                         __nv_bfloat16* __restrict__ keb)
{
    int idx = blockIdx.x * 256 + threadIdx.x;
    if (idx >= 1600 * 80) return;
    int row = idx / 80, m = idx - row * 80;
    float v = part[idx] + part[128000 + idx] + part[256000 + idx] + part[384000 + idx]
            + bias[m];
    keb[(size_t)row * 128 + m] = __float2bfloat16(v);
}

// ================= generic time-major conv/GEMM on mma.sync ================
// Y[b][t][m] = act( bias[m] + sum_{tap,c} W[(b)][tap][m][c] * X[b][t+tap-PAD][c] )
// CTA tile: 128 t x 80 m. 8 warps = 4(t) x 2(m); warp 32t x 40m (2x5 m16n8k16).
// OUT=0 bf16+bias(+relu); OUT=1 fp32+bias; OUT=2 fp32 partial (no bias, slice z).
// ZMODE=0: blockIdx.z = batch; ZMODE=1: blockIdx.z = K-slice (merged batch).

template <int TAPS, bool RELU, int OUT, int ZMODE>
__global__ void __launch_bounds__(256) convmma_kernel(
    const __nv_bfloat16* __restrict__ X, const __nv_bfloat16* __restrict__ W,
    const float* __restrict__ bias, void* __restrict__ Yv,
    int N_t, int Mtot, int Cpad, int nChunks, int wbstride, int ystride)
{
    constexpr int PAD   = (TAPS - 1) / 2;
    constexpr int AROWS = 128 + TAPS - 1;
    constexpr int ABUF  = AROWS * 128;
    constexpr int BROWS = TAPS * 80;
    constexpr int BBUF  = BROWS * 128;
    constexpr int BUF   = ABUF + BBUF;

    extern __shared__ char smem[];
    const uint32_t sbase = smem_u32(smem);
    const int tid  = threadIdx.x;
    const int lane = tid & 31;
    const int wid  = tid >> 5;
    const int t0   = blockIdx.x * 128;
    const int m0   = blockIdx.y * 80;
    const int b    = ZMODE ? 0 : blockIdx.z;
    const int kb   = ZMODE ? blockIdx.z * nChunks : 0;

    const int t_off = (wid & 3) * 32;
    const int m_off = (wid >> 2) * 40;

    const __nv_bfloat16* xb = X + (size_t)b * N_t * Cpad;
    const __nv_bfloat16* wb = W + (size_t)b * wbstride;

    float acc[2][5][4];
#pragma unroll
    for (int mt = 0; mt < 2; mt++)
#pragma unroll
        for (int nt = 0; nt < 5; nt++)
#pragma unroll
            for (int r = 0; r < 4; r++) acc[mt][nt][r] = 0.f;

    auto fill = [&](int buf, int chunk) {
        const int c0 = (kb + chunk) * 64;
        const uint32_t base = sbase + buf * BUF;
        for (int i = tid; i < AROWS * 8; i += 256) {
            int row = i >> 3, seg = i & 7;
            int t = t0 + row - PAD;
            int tc = t < 0 ? 0 : (t >= N_t ? N_t - 1 : t);
            const void* src = xb + (size_t)tc * Cpad + c0 + seg * 8;
            int sz = (t >= 0 && t < N_t) ? 16 : 0;
            cp16(base + row * 128 + ((seg ^ (row & 7)) * 16), src, sz);
        }
        for (int i = tid; i < BROWS * 8; i += 256) {
            int row = i >> 3, seg = i & 7;
            int tap = row / 80;
            int m = m0 + (row - tap * 80);
            int mc = m < Mtot ? m : Mtot - 1;
            const void* src = wb + ((size_t)tap * Mtot + mc) * Cpad + c0 + seg * 8;
            int sz = (m < Mtot) ? 16 : 0;
            cp16(base + ABUF + row * 128 + ((seg ^ (row & 7)) * 16), src, sz);
        }
        CP_COMMIT();
    };

    fill(0, 0);
    const int matm = lane >> 3;
    const int lrow = lane & 7;

    for (int s = 0; s < nChunks; s++) {
        const int cur = s & 1;
        if (s + 1 < nChunks) {
            fill(cur ^ 1, s + 1);
            asm volatile("cp.async.wait_group 1;" ::: "memory");
        } else {
            asm volatile("cp.async.wait_group 0;" ::: "memory");
        }
        __syncthreads();

        const uint32_t aA = sbase + cur * BUF;
        const uint32_t aB = aA + ABUF;
#pragma unroll
        for (int tap = 0; tap < TAPS; tap++) {
#pragma unroll
            for (int ks = 0; ks < 4; ks++) {
                uint32_t afr[2][4];
#pragma unroll
                for (int mt = 0; mt < 2; mt++) {
                    int r = t_off + mt * 16 + (matm & 1) * 8 + lrow + tap;
                    int seg = ks * 2 + (matm >> 1);
                    ldmx4(afr[mt], aA + r * 128 + ((seg ^ (r & 7)) * 16));
                }
                uint32_t bfr[5][2];
#pragma unroll
                for (int nt = 0; nt < 5; nt++) {
                    int r = tap * 80 + m_off + nt * 8 + lrow;
                    int seg = ks * 2 + (matm & 1);
                    ldmx2(bfr[nt], aB + r * 128 + ((seg ^ (r & 7)) * 16));
                }
#pragma unroll
                for (int mt = 0; mt < 2; mt++)
#pragma unroll
                    for (int nt = 0; nt < 5; nt++)
                        mma16816(acc[mt][nt], afr[mt], bfr[nt]);
            }
        }
        __syncthreads();
    }

    // epilogue: rows = time, cols = out-channels
    const int g = lane >> 2, tg = lane & 3;
#pragma unroll
    for (int mt = 0; mt < 2; mt++) {
#pragma unroll
        for (int half = 0; half < 2; half++) {
            const int t = t0 + t_off + mt * 16 + g + half * 8;
            if (t >= N_t) continue;
#pragma unroll
            for (int nt = 0; nt < 5; nt++) {
                const int m = m0 + m_off + nt * 8 + tg * 2;
                if (m >= Mtot) continue;
                if (OUT == 2) {
                    float2* y = (float2*)((float*)Yv +
                        ((size_t)blockIdx.z * N_t + t) * ystride + m);
                    *y = make_float2(acc[mt][nt][half * 2 + 0], acc[mt][nt][half * 2 + 1]);
                } else {
                    float v0 = acc[mt][nt][half * 2 + 0] + bias[m];
                    float v1 = acc[mt][nt][half * 2 + 1] + bias[m + 1];
                    if (RELU) { v0 = fmaxf(v0, 0.f); v1 = fmaxf(v1, 0.f); }
                    if (OUT == 0) {
                        __nv_bfloat162* y = (__nv_bfloat162*)
                            ((__nv_bfloat16*)Yv + ((size_t)b * N_t + t) * ystride + m);
                        *y = __floats2bfloat162_rn(v0, v1);
                    } else {
                        float2* y = (float2*)
                            ((float*)Yv + ((size_t)b * N_t + t) * ystride + m);
                        *y = make_float2(v0, v1);
                    }
                }
            }
        }
    }
}

// ===================== softmax stage: warp per row =========================
// sc[j] = -5e-4*(nq + nk[j] - 2*G[row][j]); log_softmax + prior; masked softmax.
__global__ void __launch_bounds__(256)
attn2_kernel(const float* __restrict__ G, const float* __restrict__ nk,
             const __nv_bfloat16* __restrict__ qeb, const float* __restrict__ prior,
             const unsigned* __restrict__ mask, float* __restrict__ out)
{
    const int lane = threadIdx.x & 31;
    const int row  = blockIdx.x * 8 + (threadIdx.x >> 5);   // 6400 rows = b*800+i
    const int b    = row / T1n;

    // nq = sum_c qeb[row][c]^2 (c < 80), warp-cooperative
    const __nv_bfloat162* q2 = (const __nv_bfloat162*)(qeb + (size_t)row * 128);
    float nq;
    {
        float2 v = __bfloat1622float2(q2[lane]);              // idx 0..31
        float s = v.x * v.x + v.y * v.y;
        if (lane < 8) {                                        // idx 32..39
            float2 w = __bfloat1622float2(q2[32 + lane]);
            s = fmaf(w.x, w.x, fmaf(w.y, w.y, s));
        }
#pragma unroll
        for (int o = 16; o > 0; o >>= 1) s += __shfl_xor_sync(0xffffffffu, s, o);
        nq = s;
    }

    const float* Grow = G + (size_t)row * T2n;
    const float* nkb  = nk + b * T2n;

    float sc[7];
#pragma unroll
    for (int k = 0; k < 7; k++) {
        int j = lane + k * 32;
        sc[k] = (j < T2n)
              ? -5e-4f * (nq + nkb[j] - 2.f * Grow[j])
              : -1e30f;
    }
    float mx = sc[0];
#pragma unroll
    for (int k = 1; k < 7; k++) mx = fmaxf(mx, sc[k]);
#pragma unroll
    for (int o = 16; o > 0; o >>= 1) mx = fmaxf(mx, __shfl_xor_sync(0xffffffffu, mx, o));
    float se = 0.f;
#pragma unroll
    for (int k = 0; k < 7; k++) se += __expf(sc[k] - mx);
#pragma unroll
    for (int o = 16; o > 0; o >>= 1) se += __shfl_xor_sync(0xffffffffu, se, o);
    const float lse = mx + __logf(se);

    const size_t base = (size_t)row * T2n;
    const float* prow = prior + base;
    float lp[7];
    bool  keep[7];
#pragma unroll
    for (int k = 0; k < 7; k++) {
        int j = lane + k * 32;
        if (j < T2n) {
            lp[k] = sc[k] - lse + __logf(prow[j] + 1e-8f);
            out[(size_t)Bn * T1n * T2n + base + j] = lp[k];
            keep[k] = (mask[b * T2n + j] == 0u);
        } else { lp[k] = -1e30f; keep[k] = false; }
    }

    float m2 = -1e30f;
#pragma unroll
    for (int k = 0; k < 7; k++) if (keep[k]) m2 = fmaxf(m2, lp[k]);
#pragma unroll
    for (int o = 16; o > 0; o >>= 1) m2 = fmaxf(m2, __shfl_xor_sync(0xffffffffu, m2, o));
    float s2 = 0.f;
#pragma unroll
    for (int k = 0; k < 7; k++) if (keep[k]) s2 += __expf(lp[k] - m2);
#pragma unroll
    for (int o = 16; o > 0; o >>= 1) s2 += __shfl_xor_sync(0xffffffffu, s2, o);

#pragma unroll
    for (int k = 0; k < 7; k++) {
        int j = lane + k * 32;
        if (j < T2n)
            out[base + j] = keep[k] ? __expf(lp[k] - m2) / s2 : 0.f;
    }
}

// ---------------------------------------------------------------------------

static void* sym_addr(const void* sym)
{
    void* p = nullptr;
    cudaGetSymbolAddress(&p, sym);
    return p;
}

#define SMEM_T3 (2 * (130 + 240) * 128)   // 94720
#define SMEM_T1 (2 * (128 + 80) * 128)    // 53248

extern "C" void kernel_launch(void* const* d_in, const int* in_sizes, int n_in,
                              void* d_out, int out_size)
{
    const float*    queries = (const float*)d_in[0];
    const float*    keys    = (const float*)d_in[1];
    const unsigned* mask    = (const unsigned*)d_in[3];
    const float*    prior   = (const float*)d_in[4];
    const float*    kp_w1   = (const float*)d_in[5];
    const float*    kp_b1   = (const float*)d_in[6];
    const float*    kp_w2   = (const float*)d_in[7];
    const float*    kp_b2   = (const float*)d_in[8];
    const float*    qp_w1   = (const float*)d_in[9];
    const float*    qp_b1   = (const float*)d_in[10];
    const float*    qp_w2   = (const float*)d_in[11];
    const float*    qp_b2   = (const float*)d_in[12];
    const float*    qp_w3   = (const float*)d_in[13];
    const float*    qp_b3   = (const float*)d_in[14];
    float* out = (float*)d_out;

    __nv_bfloat16* xt  = (__nv_bfloat16*)sym_addr(g_xt);
    __nv_bfloat16* xq  = (__nv_bfloat16*)sym_addr(g_xq);
    __nv_bfloat16* h1  = (__nv_bfloat16*)sym_addr(g_h1);
    __nv_bfloat16* keb = (__nv_bfloat16*)sym_addr(g_keb);
    __nv_bfloat16* hq1 = (__nv_bfloat16*)sym_addr(g_hq1);
    __nv_bfloat16* hq2 = (__nv_bfloat16*)sym_addr(g_hq2);
    __nv_bfloat16* qeb = (__nv_bfloat16*)sym_addr(g_qeb);
    __nv_bfloat16* wt  = (__nv_bfloat16*)sym_addr(g_wt);
    __nv_bfloat16* wk2 = (__nv_bfloat16*)sym_addr(g_wk2);
    __nv_bfloat16* wq1 = (__nv_bfloat16*)sym_addr(g_wq1);
    __nv_bfloat16* wq2 = (__nv_bfloat16*)sym_addr(g_wq2);
    __nv_bfloat16* wq3 = (__nv_bfloat16*)sym_addr(g_wq3);
    float* part = (float*)sym_addr(g_part);
    float* G    = (float*)sym_addr(g_G);
    float* nk   = (float*)sym_addr(g_nk);
    float* zb   = (float*)sym_addr(g_zbias);

    static bool attr_set = false;
    if (!attr_set) {
        cudaFuncSetAttribute(convmma_kernel<3, true, 0, 0>,
                             cudaFuncAttributeMaxDynamicSharedMemorySize, SMEM_T3);
        cudaFuncSetAttribute(convmma_kernel<1, true, 0, 0>,
                             cudaFuncAttributeMaxDynamicSharedMemorySize, SMEM_T1);
        cudaFuncSetAttribute(convmma_kernel<1, false, 0, 0>,
                             cudaFuncAttributeMaxDynamicSharedMemorySize, SMEM_T1);
        cudaFuncSetAttribute(convmma_kernel<1, false, 1, 0>,
                             cudaFuncAttributeMaxDynamicSharedMemorySize, SMEM_T1);
        cudaFuncSetAttribute(convmma_kernel<1, false, 2, 1>,
                             cudaFuncAttributeMaxDynamicSharedMemorySize, SMEM_T1);
        attr_set = true;
    }

    // ---- preps (2 transposes + 1 fused weight conversion) ----
    prep_weights_kernel<<<(WP0 + WP1 + WP2 + WP3 + WP4 + 255) / 256, 256>>>(
        kp_w1, kp_w2, qp_w1, qp_w2, qp_w3, wt, wk2, wq1, wq2, wq3);
    prep_xpose_kernel<<<dim3(7, 16, 8), dim3(32, 8)>>>(keys, xt, 512, T2n, 512);
    prep_xpose_kernel<<<dim3(25, 4, 8), dim3(32, 8)>>>(queries, xq, 80, T1n, 128);

    // ---- key projection ----
    // kp1: 512->1024 k3, time-major, per batch. grid (t=2, m=13, b=8)
    convmma_kernel<3, true, 0, 0><<<dim3(2, 13, 8), 256, SMEM_T3>>>(
        xt, wt, kp_b1, h1, T2n, 1024, 512, 8, 0, 1024);
    // kp2: 1024->80 k1, merged batch (N=1600), split-K x4. grid (13,1,4)
    convmma_kernel<1, false, 2, 1><<<dim3(13, 1, 4), 256, SMEM_T1>>>(
        h1, wk2, zb, part, 1600, 80, 1024, 4, 0, 80);
    reduce_kp2_kernel<<<(1600 * 80 + 255) / 256, 256>>>(part, kp_b2, keb);

    // ---- query projection chain ----
    convmma_kernel<3, true, 0, 0><<<dim3(7, 2, 8), 256, SMEM_T3>>>(
        xq, wq1, qp_b1, hq1, T1n, 160, 128, 2, 0, 192);
    convmma_kernel<1, true, 0, 0><<<dim3(50, 1, 1), 256, SMEM_T1>>>(
        hq1, wq2, qp_b2, hq2, 6400, 80, 192, 3, 0, 128);
    convmma_kernel<1, false, 0, 0><<<dim3(50, 1, 1), 256, SMEM_T1>>>(
        hq2, wq3, qp_b3, qeb, 6400, 80, 128, 2, 0, 128);

    // ---- Gram matrix G = qe . ke^T (keb acts as per-batch "weights") ----
    convmma_kernel<1, false, 1, 0><<<dim3(7, 3, 8), 256, SMEM_T1>>>(
        qeb, keb, zb, G, T1n, T2n, 128, 2, T2n * 128, T2n);

    // ---- nk norms + softmax stage ----
    norms_kernel<<<(8 * T2n + 255) / 256, 256>>>(keb, nk, 8 * T2n);
    attn2_kernel<<<800, 256>>>(G, nk, qeb, prior, mask, out);
}

// round 8
// speedup vs baseline: 8.3420x; 1.1315x over previous
#include <cuda_runtime.h>
#include <cuda_bf16.h>
#include <cstdint>

// ---------------------------------------------------------------------------
// ConvAttention, R7: guard-row batch merging for k=3 convs, hoisted cp.async
// fills, ldmatrix.x4 B fragments, fused kp2-reduce + key norms.
// Layouts:
//   guarded signal: rows [b*(T+1)+1 .. b*(T+1)+T], zero guard row between
//   batches (zero-init __device__ globals, never written) == conv zero-pad.
//   1-tap consumers map valid row i -> i + i/L + 1 (L = per-batch length).
// ---------------------------------------------------------------------------

#define Bn   8
#define T1n  800
#define T2n  200

// -------- scratch (device globals; zero-initialized, guards never written) --
__device__ __nv_bfloat16 g_xt [1664 * 512];      // keys guarded [1609+pad][512]
__device__ __nv_bfloat16 g_xq [6528 * 128];      // queries guarded [6409+pad][128]
__device__ __nv_bfloat16 g_h1 [1664 * 1024];     // kp1 out, guard layout
__device__ __nv_bfloat16 g_keb[1600 * 128];      // key emb plain (pads stay 0)
__device__ __nv_bfloat16 g_hq1[6528 * 192];      // qp1 out, guard layout
__device__ __nv_bfloat16 g_hq2[6400 * 128];      // qp2 out plain
__device__ __nv_bfloat16 g_qeb[6400 * 128];      // query emb plain
__device__ __nv_bfloat16 g_wt [3 * 1024 * 512];  // kp_w1 [tap][m][512]
__device__ __nv_bfloat16 g_wk2[80 * 1024];
__device__ __nv_bfloat16 g_wq1[3 * 160 * 128];
__device__ __nv_bfloat16 g_wq2[80 * 192];
__device__ __nv_bfloat16 g_wq3[80 * 128];
__device__ float g_part[4 * 1600 * 80];          // kp2 split-K partials
__device__ float g_G  [8 * 800 * 200];
__device__ float g_nk [8 * 200];
__device__ float g_zbias[256];

// ========================= inline PTX helpers ==============================

__device__ __forceinline__ uint32_t smem_u32(const void* p) {
    uint32_t a;
    asm("{ .reg .u64 t; cvta.to.shared.u64 t, %1; cvt.u32.u64 %0, t; }"
        : "=r"(a) : "l"(p));
    return a;
}
__device__ __forceinline__ void cp16(uint32_t dst, const void* src, int sz) {
    asm volatile("cp.async.cg.shared.global [%0], [%1], 16, %2;"
                 :: "r"(dst), "l"(src), "r"(sz) : "memory");
}
#define CP_COMMIT() asm volatile("cp.async.commit_group;" ::: "memory")

__device__ __forceinline__ void ldmx4(uint32_t* r, uint32_t addr) {
    asm volatile("ldmatrix.sync.aligned.m8n8.x4.shared.b16 {%0,%1,%2,%3}, [%4];"
                 : "=r"(r[0]), "=r"(r[1]), "=r"(r[2]), "=r"(r[3]) : "r"(addr));
}
__device__ __forceinline__ void ldmx2(uint32_t* r, uint32_t addr) {
    asm volatile("ldmatrix.sync.aligned.m8n8.x2.shared.b16 {%0,%1}, [%2];"
                 : "=r"(r[0]), "=r"(r[1]) : "r"(addr));
}
__device__ __forceinline__ void mma16816(float* c, const uint32_t* a, const uint32_t* bq) {
    asm volatile(
        "mma.sync.aligned.m16n8k16.row.col.f32.bf16.bf16.f32 "
        "{%0,%1,%2,%3}, {%4,%5,%6,%7}, {%8,%9}, {%0,%1,%2,%3};"
        : "+f"(c[0]), "+f"(c[1]), "+f"(c[2]), "+f"(c[3])
        : "r"(a[0]), "r"(a[1]), "r"(a[2]), "r"(a[3]), "r"(bq[0]), "r"(bq[1]));
}

// ============================ prep kernels =================================

__device__ __forceinline__ void wprep_one(const float* W, __nv_bfloat16* Wt,
                                          int idx, int M, int Cin, int Cpad, int taps)
{
    int c = idx % Cpad;
    int r = idx / Cpad;
    int m = r % M;
    int tap = r / M;
    float v = (c < Cin) ? W[((size_t)m * Cin + c) * taps + tap] : 0.f;
    Wt[idx] = __float2bfloat16(v);
}

#define WP0 (3 * 1024 * 512)
#define WP1 (80 * 1024)
#define WP2 (3 * 160 * 128)
#define WP3 (80 * 192)
#define WP4 (80 * 128)
__global__ void __launch_bounds__(256) prep_weights_kernel(
    const float* __restrict__ w1, const float* __restrict__ w2,
    const float* __restrict__ q1, const float* __restrict__ q2,
    const float* __restrict__ q3,
    __nv_bfloat16* __restrict__ o1, __nv_bfloat16* __restrict__ o2,
    __nv_bfloat16* __restrict__ o3, __nv_bfloat16* __restrict__ o4,
    __nv_bfloat16* __restrict__ o5)
{
    int idx = blockIdx.x * 256 + threadIdx.x;
    if (idx < WP0) { wprep_one(w1, o1, idx, 1024, 512, 512, 3); return; }
    idx -= WP0;
    if (idx < WP1) { wprep_one(w2, o2, idx, 80, 1024, 1024, 1); return; }
    idx -= WP1;
    if (idx < WP2) { wprep_one(q1, o3, idx, 160, 80, 128, 3); return; }
    idx -= WP2;
    if (idx < WP3) { wprep_one(q2, o4, idx, 80, 160, 192, 1); return; }
    idx -= WP3;
    if (idx < WP4) { wprep_one(q3, o5, idx, 80, 80, 128, 1); }
}

// X (B, C, T) fp32 -> guarded [b*(T+1)+1+t][Cpad] bf16 (zero pad cols)
__global__ void __launch_bounds__(256) prep_xpose_kernel(const float* __restrict__ X,
                                                         __nv_bfloat16* __restrict__ Xt,
                                                         int C, int T, int Cpad)
{
    __shared__ float tile[32][33];
    const int b  = blockIdx.z;
    const int t0 = blockIdx.x * 32;
    const int c0 = blockIdx.y * 32;
    const int tx = threadIdx.x, ty = threadIdx.y;
    const float* xb = X + (size_t)b * C * T;
#pragma unroll
    for (int j = 0; j < 32; j += 8) {
        int c = c0 + ty + j, t = t0 + tx;
        tile[ty + j][tx] = (c < C && t < T) ? xb[(size_t)c * T + t] : 0.f;
    }
    __syncthreads();
    __nv_bfloat16* xo = Xt + ((size_t)b * (T + 1) + 1) * Cpad;
#pragma unroll
    for (int j = 0; j < 32; j += 8) {
        int t = t0 + ty + j, c = c0 + tx;
        if (t < T && c < Cpad) xo[(size_t)t * Cpad + c] = __float2bfloat16(tile[tx][ty + j]);
    }
}

// fused kp2 split-K reduce + key norms; warp per row (1600 rows)
__global__ void __launch_bounds__(256) reduce_kp2_norms_kernel(
    const float* __restrict__ part, const float* __restrict__ bias,
    __nv_bfloat16* __restrict__ keb, float* __restrict__ nk)
{
    const int lane = threadIdx.x & 31;
    const int row  = blockIdx.x * 8 + (threadIdx.x >> 5);
    float sq = 0.f;
#pragma unroll
    for (int k = 0; k < 3; k++) {
        int m = lane + k * 32;
        if (m < 80) {
            int idx = row * 80 + m;
            float v = part[idx] + part[128000 + idx] + part[256000 + idx]
                    + part[384000 + idx] + bias[m];
            keb[(size_t)row * 128 + m] = __float2bfloat16(v);
            sq = fmaf(v, v, sq);
        }
    }
#pragma unroll
    for (int o = 16; o > 0; o >>= 1) sq += __shfl_xor_sync(0xffffffffu, sq, o);
    if (lane == 0) nk[row] = sq;
}

// ================= generic time-major conv/GEMM on mma.sync ================
// CTA tile: 128 t x 80 m. 8 warps = 4(t) x 2(m); warp 32t x 40m (2x5 m16n8k16).
// OUT=0 bf16+bias(+relu); OUT=1 fp32+bias; OUT=2 fp32 partial (slice z).
// ZMODE=0: z = batch (or 1 for merged); ZMODE=1: z = K-slice.
// L>0: A rows map i -> i + i/L + 1 (guarded input, 1-tap only).

template <int TAPS, bool RELU, int OUT, int ZMODE>
__global__ void __launch_bounds__(256) convmma_kernel(
    const __nv_bfloat16* __restrict__ X, const __nv_bfloat16* __restrict__ W,
    const float* __restrict__ bias, void* __restrict__ Yv,
    int N_t, int Mtot, int Cpad, int nChunks, int wbstride, int ystride, int L)
{
    constexpr int PAD   = (TAPS - 1) / 2;
    constexpr int AROWS = 128 + TAPS - 1;
    constexpr int ABUF  = AROWS * 128;
    constexpr int BROWS = TAPS * 80;
    constexpr int BBUF  = BROWS * 128;
    constexpr int BUF   = ABUF + BBUF + 16;      // +16B trash slot per buffer
    constexpr int nA    = (AROWS * 8 + 255) / 256;
    constexpr int nB    = (BROWS * 8 + 255) / 256;

    extern __shared__ char smem[];
    const uint32_t sbase = smem_u32(smem);
    const int tid  = threadIdx.x;
    const int lane = tid & 31;
    const int wid  = tid >> 5;
    const int t0   = blockIdx.x * 128;
    const int m0   = blockIdx.y * 80;
    const int b    = ZMODE ? 0 : blockIdx.z;
    const int kb   = ZMODE ? blockIdx.z * nChunks : 0;

    const int t_off = (wid & 3) * 32;
    const int m_off = (wid >> 2) * 40;

    const __nv_bfloat16* xb = X + (size_t)b * N_t * Cpad;
    const __nv_bfloat16* wb = W + (size_t)b * wbstride;

    // ---- hoisted fill descriptors (chunk-invariant) ----
    const char* srcA[nA]; uint32_t offA[nA];
    const char* srcB[nB]; uint32_t offB[nB];
    unsigned mA = 0, mB = 0;
#pragma unroll
    for (int k = 0; k < nA; k++) {
        int idx = tid + k * 256;
        if (idx < AROWS * 8) {
            int row = idx >> 3, seg = idx & 7;
            int t = t0 + row - PAD;
            int xrow; bool ok;
            if (TAPS == 3) {
                xrow = t < 0 ? 0 : (t >= N_t ? N_t - 1 : t);
                ok = true;
            } else {
                ok = t < N_t;
                int i = ok ? t : N_t - 1;
                xrow = L ? (i + i / L + 1) : i;
            }
            srcA[k] = (const char*)(xb + (size_t)xrow * Cpad + kb * 64) + seg * 16;
            offA[k] = row * 128 + ((seg ^ (row & 7)) * 16);
            if (ok) mA |= 1u << k;
        } else {
            srcA[k] = (const char*)xb;
            offA[k] = ABUF + BBUF;               // trash
        }
    }
#pragma unroll
    for (int k = 0; k < nB; k++) {
        int idx = tid + k * 256;
        if (idx < BROWS * 8) {
            int row = idx >> 3, seg = idx & 7;
            int tap = row / 80;
            int m = m0 + (row - tap * 80);
            int mc = m < Mtot ? m : Mtot - 1;
            srcB[k] = (const char*)(wb + ((size_t)tap * Mtot + mc) * Cpad + kb * 64) + seg * 16;
            offB[k] = ABUF + row * 128 + ((seg ^ (row & 7)) * 16);
            if (m < Mtot) mB |= 1u << k;
        } else {
            srcB[k] = (const char*)wb;
            offB[k] = ABUF + BBUF;               // trash
        }
    }

    float acc[2][5][4];
#pragma unroll
    for (int mt = 0; mt < 2; mt++)
#pragma unroll
        for (int nt = 0; nt < 5; nt++)
#pragma unroll
            for (int r = 0; r < 4; r++) acc[mt][nt][r] = 0.f;

    auto fill = [&](int buf, int chunk) {
        const uint32_t base = sbase + buf * BUF;
        const int co = chunk * 128;
#pragma unroll
        for (int k = 0; k < nA; k++)
            cp16(base + offA[k], srcA[k] + co, ((mA >> k) & 1) << 4);
#pragma unroll
        for (int k = 0; k < nB; k++)
            cp16(base + offB[k], srcB[k] + co, ((mB >> k) & 1) << 4);
        CP_COMMIT();
    };

    fill(0, 0);
    const int matm = lane >> 3;
    const int lrow = lane & 7;

    for (int s = 0; s < nChunks; s++) {
        const int cur = s & 1;
        if (s + 1 < nChunks) {
            fill(cur ^ 1, s + 1);
            asm volatile("cp.async.wait_group 1;" ::: "memory");
        } else {
            asm volatile("cp.async.wait_group 0;" ::: "memory");
        }
        __syncthreads();

        const uint32_t aA = sbase + cur * BUF;
        const uint32_t aB = aA + ABUF;
#pragma unroll
        for (int tap = 0; tap < TAPS; tap++) {
#pragma unroll
            for (int ks = 0; ks < 4; ks++) {
                uint32_t afr[2][4];
#pragma unroll
                for (int mt = 0; mt < 2; mt++) {
                    int r = t_off + mt * 16 + (matm & 1) * 8 + lrow + tap;
                    int seg = ks * 2 + (matm >> 1);
                    ldmx4(afr[mt], aA + r * 128 + ((seg ^ (r & 7)) * 16));
                }
                uint32_t bfr[5][2];
#pragma unroll
                for (int np = 0; np < 2; np++) {            // nt pairs via x4
                    int r = tap * 80 + m_off + (2 * np + (matm >> 1)) * 8 + lrow;
                    int seg = ks * 2 + (matm & 1);
                    uint32_t tmp[4];
                    ldmx4(tmp, aB + r * 128 + ((seg ^ (r & 7)) * 16));
                    bfr[2 * np][0] = tmp[0]; bfr[2 * np][1] = tmp[1];
                    bfr[2 * np + 1][0] = tmp[2]; bfr[2 * np + 1][1] = tmp[3];
                }
                {                                            // nt = 4 via x2
                    int r = tap * 80 + m_off + 32 + lrow;
                    int seg = ks * 2 + (matm & 1);
                    ldmx2(bfr[4], aB + r * 128 + ((seg ^ (r & 7)) * 16));
                }
#pragma unroll
                for (int mt = 0; mt < 2; mt++)
#pragma unroll
                    for (int nt = 0; nt < 5; nt++)
                        mma16816(acc[mt][nt], afr[mt], bfr[nt]);
            }
        }
        __syncthreads();
    }

    // epilogue
    const int g = lane >> 2, tg = lane & 3;
#pragma unroll
    for (int mt = 0; mt < 2; mt++) {
#pragma unroll
        for (int half = 0; half < 2; half++) {
            const int t = t0 + t_off + mt * 16 + g + half * 8;
            if (t >= N_t) continue;
#pragma unroll
            for (int nt = 0; nt < 5; nt++) {
                const int m = m0 + m_off + nt * 8 + tg * 2;
                if (m >= Mtot) continue;
                if (OUT == 2) {
                    float2* y = (float2*)((float*)Yv +
                        ((size_t)blockIdx.z * N_t + t) * ystride + m);
                    *y = make_float2(acc[mt][nt][half * 2 + 0], acc[mt][nt][half * 2 + 1]);
                } else {
                    float v0 = acc[mt][nt][half * 2 + 0] + bias[m];
                    float v1 = acc[mt][nt][half * 2 + 1] + bias[m + 1];
                    if (RELU) { v0 = fmaxf(v0, 0.f); v1 = fmaxf(v1, 0.f); }
                    if (OUT == 0) {
                        __nv_bfloat162* y = (__nv_bfloat162*)
                            ((__nv_bfloat16*)Yv + ((size_t)b * N_t + t) * ystride + m);
                        *y = __floats2bfloat162_rn(v0, v1);
                    } else {
                        float2* y = (float2*)
                            ((float*)Yv + ((size_t)b * N_t + t) * ystride + m);
                        *y = make_float2(v0, v1);
                    }
                }
            }
        }
    }
}

// ===================== softmax stage: warp per row =========================
__global__ void __launch_bounds__(256)
attn2_kernel(const float* __restrict__ G, const float* __restrict__ nk,
             const __nv_bfloat16* __restrict__ qeb, const float* __restrict__ prior,
             const unsigned* __restrict__ mask, float* __restrict__ out)
{
    const int lane = threadIdx.x & 31;
    const int row  = blockIdx.x * 8 + (threadIdx.x >> 5);   // b*800+i
    const int b    = row / T1n;

    const __nv_bfloat162* q2 = (const __nv_bfloat162*)(qeb + (size_t)row * 128);
    float nq;
    {
        float2 v = __bfloat1622float2(q2[lane]);
        float s = v.x * v.x + v.y * v.y;
        if (lane < 8) {
            float2 w = __bfloat1622float2(q2[32 + lane]);
            s = fmaf(w.x, w.x, fmaf(w.y, w.y, s));
        }
#pragma unroll
        for (int o = 16; o > 0; o >>= 1) s += __shfl_xor_sync(0xffffffffu, s, o);
        nq = s;
    }

    const float* Grow = G + (size_t)row * T2n;
    const float* nkb  = nk + b * T2n;

    float sc[7];
#pragma unroll
    for (int k = 0; k < 7; k++) {
        int j = lane + k * 32;
        sc[k] = (j < T2n) ? -5e-4f * (nq + nkb[j] - 2.f * Grow[j]) : -1e30f;
    }
    float mx = sc[0];
#pragma unroll
    for (int k = 1; k < 7; k++) mx = fmaxf(mx, sc[k]);
#pragma unroll
    for (int o = 16; o > 0; o >>= 1) mx = fmaxf(mx, __shfl_xor_sync(0xffffffffu, mx, o));
    float se = 0.f;
#pragma unroll
    for (int k = 0; k < 7; k++) se += __expf(sc[k] - mx);
#pragma unroll
    for (int o = 16; o > 0; o >>= 1) se += __shfl_xor_sync(0xffffffffu, se, o);
    const float lse = mx + __logf(se);

    const size_t base = (size_t)row * T2n;
    const float* prow = prior + base;
    float lp[7];
    bool  keep[7];
#pragma unroll
    for (int k = 0; k < 7; k++) {
        int j = lane + k * 32;
        if (j < T2n) {
            lp[k] = sc[k] - lse + __logf(prow[j] + 1e-8f);
            out[(size_t)Bn * T1n * T2n + base + j] = lp[k];
            keep[k] = (mask[b * T2n + j] == 0u);
        } else { lp[k] = -1e30f; keep[k] = false; }
    }

    float m2 = -1e30f;
#pragma unroll
    for (int k = 0; k < 7; k++) if (keep[k]) m2 = fmaxf(m2, lp[k]);
#pragma unroll
    for (int o = 16; o > 0; o >>= 1) m2 = fmaxf(m2, __shfl_xor_sync(0xffffffffu, m2, o));
    float s2 = 0.f;
#pragma unroll
    for (int k = 0; k < 7; k++) if (keep[k]) s2 += __expf(lp[k] - m2);
#pragma unroll
    for (int o = 16; o > 0; o >>= 1) s2 += __shfl_xor_sync(0xffffffffu, s2, o);

#pragma unroll
    for (int k = 0; k < 7; k++) {
        int j = lane + k * 32;
        if (j < T2n)
            out[base + j] = keep[k] ? __expf(lp[k] - m2) / s2 : 0.f;
    }
}

// ---------------------------------------------------------------------------

static void* sym_addr(const void* sym)
{
    void* p = nullptr;
    cudaGetSymbolAddress(&p, sym);
    return p;
}

#define SMEM_T3 (2 * ((130 + 240) * 128 + 16))   // 94752
#define SMEM_T1 (2 * ((128 + 80) * 128 + 16))    // 53280

extern "C" void kernel_launch(void* const* d_in, const int* in_sizes, int n_in,
                              void* d_out, int out_size)
{
    const float*    queries = (const float*)d_in[0];
    const float*    keys    = (const float*)d_in[1];
    const unsigned* mask    = (const unsigned*)d_in[3];
    const float*    prior   = (const float*)d_in[4];
    const float*    kp_w1   = (const float*)d_in[5];
    const float*    kp_b1   = (const float*)d_in[6];
    const float*    kp_w2   = (const float*)d_in[7];
    const float*    kp_b2   = (const float*)d_in[8];
    const float*    qp_w1   = (const float*)d_in[9];
    const float*    qp_b1   = (const float*)d_in[10];
    const float*    qp_w2   = (const float*)d_in[11];
    const float*    qp_b2   = (const float*)d_in[12];
    const float*    qp_w3   = (const float*)d_in[13];
    const float*    qp_b3   = (const float*)d_in[14];
    float* out = (float*)d_out;

    __nv_bfloat16* xt  = (__nv_bfloat16*)sym_addr(g_xt);
    __nv_bfloat16* xq  = (__nv_bfloat16*)sym_addr(g_xq);
    __nv_bfloat16* h1  = (__nv_bfloat16*)sym_addr(g_h1);
    __nv_bfloat16* keb = (__nv_bfloat16*)sym_addr(g_keb);
    __nv_bfloat16* hq1 = (__nv_bfloat16*)sym_addr(g_hq1);
    __nv_bfloat16* hq2 = (__nv_bfloat16*)sym_addr(g_hq2);
    __nv_bfloat16* qeb = (__nv_bfloat16*)sym_addr(g_qeb);
    __nv_bfloat16* wt  = (__nv_bfloat16*)sym_addr(g_wt);
    __nv_bfloat16* wk2 = (__nv_bfloat16*)sym_addr(g_wk2);
    __nv_bfloat16* wq1 = (__nv_bfloat16*)sym_addr(g_wq1);
    __nv_bfloat16* wq2 = (__nv_bfloat16*)sym_addr(g_wq2);
    __nv_bfloat16* wq3 = (__nv_bfloat16*)sym_addr(g_wq3);
    float* part = (float*)sym_addr(g_part);
    float* G    = (float*)sym_addr(g_G);
    float* nk   = (float*)sym_addr(g_nk);
    float* zb   = (float*)sym_addr(g_zbias);

    static bool attr_set = false;
    if (!attr_set) {
        cudaFuncSetAttribute(convmma_kernel<3, true, 0, 0>,
                             cudaFuncAttributeMaxDynamicSharedMemorySize, SMEM_T3);
        cudaFuncSetAttribute(convmma_kernel<1, true, 0, 0>,
                             cudaFuncAttributeMaxDynamicSharedMemorySize, SMEM_T1);
        cudaFuncSetAttribute(convmma_kernel<1, false, 0, 0>,
                             cudaFuncAttributeMaxDynamicSharedMemorySize, SMEM_T1);
        cudaFuncSetAttribute(convmma_kernel<1, false, 1, 0>,
                             cudaFuncAttributeMaxDynamicSharedMemorySize, SMEM_T1);
        cudaFuncSetAttribute(convmma_kernel<1, false, 2, 1>,
                             cudaFuncAttributeMaxDynamicSharedMemorySize, SMEM_T1);
        attr_set = true;
    }

    // ---- preps ----
    prep_weights_kernel<<<(WP0 + WP1 + WP2 + WP3 + WP4 + 255) / 256, 256>>>(
        kp_w1, kp_w2, qp_w1, qp_w2, qp_w3, wt, wk2, wq1, wq2, wq3);
    prep_xpose_kernel<<<dim3(7, 16, 8), dim3(32, 8)>>>(keys, xt, 512, T2n, 512);
    prep_xpose_kernel<<<dim3(25, 4, 8), dim3(32, 8)>>>(queries, xq, 80, T1n, 128);

    // ---- key projection ----
    // kp1: guard-merged, N_t = 8*201+1 = 1609. grid (13 t, 13 m, 1)
    convmma_kernel<3, true, 0, 0><<<dim3(13, 13, 1), 256, SMEM_T3>>>(
        xt, wt, kp_b1, h1, 1609, 1024, 512, 8, 0, 1024, 0);
    // kp2: 1024->80, merged valid rows (1600), rowmap L=200, split-K x4
    convmma_kernel<1, false, 2, 1><<<dim3(13, 1, 4), 256, SMEM_T1>>>(
        h1, wk2, zb, part, 1600, 80, 1024, 4, 0, 80, 200);
    reduce_kp2_norms_kernel<<<200, 256>>>(part, kp_b2, keb, nk);

    // ---- query projection chain ----
    // qp1: guard-merged, N_t = 8*801+1 = 6409. grid (51, 2, 1)
    convmma_kernel<3, true, 0, 0><<<dim3(51, 2, 1), 256, SMEM_T3>>>(
        xq, wq1, qp_b1, hq1, 6409, 160, 128, 2, 0, 192, 0);
    // qp2: reads guarded hq1 via L=800, writes plain hq2
    convmma_kernel<1, true, 0, 0><<<dim3(50, 1, 1), 256, SMEM_T1>>>(
        hq1, wq2, qp_b2, hq2, 6400, 80, 192, 3, 0, 128, 800);
    // qp3: plain -> plain
    convmma_kernel<1, false, 0, 0><<<dim3(50, 1, 1), 256, SMEM_T1>>>(
        hq2, wq3, qp_b3, qeb, 6400, 80, 128, 2, 0, 128, 0);

    // ---- Gram matrix G = qe . ke^T (keb as per-batch "weights") ----
    convmma_kernel<1, false, 1, 0><<<dim3(7, 3, 8), 256, SMEM_T1>>>(
        qeb, keb, zb, G, 800, 200, 128, 2, 200 * 128, 200, 0);

    // ---- softmax stage ----
    attn2_kernel<<<800, 256>>>(G, nk, qeb, prior, mask, out);
}

// round 9
// speedup vs baseline: 8.5787x; 1.0284x over previous
#include <cuda_runtime.h>
#include <cuda_bf16.h>
#include <cstdint>

// ---------------------------------------------------------------------------
// ConvAttention, R8: convmma with u32-offset hoisted fills + launch_bounds
// (256,2) => <=128 regs => 2 CTAs/SM => kp1 single-wave with overlap.
// Guard-row batch merging as R7.
// ---------------------------------------------------------------------------

#define Bn   8
#define T1n  800
#define T2n  200

// -------- scratch (device globals; zero-initialized, guards never written) --
__device__ __nv_bfloat16 g_xt [1664 * 512];      // keys guarded [1609+pad][512]
__device__ __nv_bfloat16 g_xq [6528 * 128];      // queries guarded [6409+pad][128]
__device__ __nv_bfloat16 g_h1 [1664 * 1024];     // kp1 out, guard layout
__device__ __nv_bfloat16 g_keb[1600 * 128];      // key emb plain (pads stay 0)
__device__ __nv_bfloat16 g_hq1[6528 * 192];      // qp1 out, guard layout
__device__ __nv_bfloat16 g_hq2[6400 * 128];      // qp2 out plain
__device__ __nv_bfloat16 g_qeb[6400 * 128];      // query emb plain
__device__ __nv_bfloat16 g_wt [3 * 1024 * 512];  // kp_w1 [tap][m][512]
__device__ __nv_bfloat16 g_wk2[80 * 1024];
__device__ __nv_bfloat16 g_wq1[3 * 160 * 128];
__device__ __nv_bfloat16 g_wq2[80 * 192];
__device__ __nv_bfloat16 g_wq3[80 * 128];
__device__ float g_part[4 * 1600 * 80];          // kp2 split-K partials
__device__ float g_G  [8 * 800 * 200];
__device__ float g_nk [8 * 200];
__device__ float g_zbias[256];

// ========================= inline PTX helpers ==============================

__device__ __forceinline__ uint32_t smem_u32(const void* p) {
    uint32_t a;
    asm("{ .reg .u64 t; cvta.to.shared.u64 t, %1; cvt.u32.u64 %0, t; }"
        : "=r"(a) : "l"(p));
    return a;
}
__device__ __forceinline__ void cp16(uint32_t dst, const void* src, int sz) {
    asm volatile("cp.async.cg.shared.global [%0], [%1], 16, %2;"
                 :: "r"(dst), "l"(src), "r"(sz) : "memory");
}
#define CP_COMMIT() asm volatile("cp.async.commit_group;" ::: "memory")

__device__ __forceinline__ void ldmx4(uint32_t* r, uint32_t addr) {
    asm volatile("ldmatrix.sync.aligned.m8n8.x4.shared.b16 {%0,%1,%2,%3}, [%4];"
                 : "=r"(r[0]), "=r"(r[1]), "=r"(r[2]), "=r"(r[3]) : "r"(addr));
}
__device__ __forceinline__ void ldmx2(uint32_t* r, uint32_t addr) {
    asm volatile("ldmatrix.sync.aligned.m8n8.x2.shared.b16 {%0,%1}, [%2];"
                 : "=r"(r[0]), "=r"(r[1]) : "r"(addr));
}
__device__ __forceinline__ void mma16816(float* c, const uint32_t* a, const uint32_t* bq) {
    asm volatile(
        "mma.sync.aligned.m16n8k16.row.col.f32.bf16.bf16.f32 "
        "{%0,%1,%2,%3}, {%4,%5,%6,%7}, {%8,%9}, {%0,%1,%2,%3};"
        : "+f"(c[0]), "+f"(c[1]), "+f"(c[2]), "+f"(c[3])
        : "r"(a[0]), "r"(a[1]), "r"(a[2]), "r"(a[3]), "r"(bq[0]), "r"(bq[1]));
}

// ============================ prep kernels =================================

__device__ __forceinline__ void wprep_one(const float* W, __nv_bfloat16* Wt,
                                          int idx, int M, int Cin, int Cpad, int taps)
{
    int c = idx % Cpad;
    int r = idx / Cpad;
    int m = r % M;
    int tap = r / M;
    float v = (c < Cin) ? W[((size_t)m * Cin + c) * taps + tap] : 0.f;
    Wt[idx] = __float2bfloat16(v);
}

#define WP0 (3 * 1024 * 512)
#define WP1 (80 * 1024)
#define WP2 (3 * 160 * 128)
#define WP3 (80 * 192)
#define WP4 (80 * 128)
__global__ void __launch_bounds__(256) prep_weights_kernel(
    const float* __restrict__ w1, const float* __restrict__ w2,
    const float* __restrict__ q1, const float* __restrict__ q2,
    const float* __restrict__ q3,
    __nv_bfloat16* __restrict__ o1, __nv_bfloat16* __restrict__ o2,
    __nv_bfloat16* __restrict__ o3, __nv_bfloat16* __restrict__ o4,
    __nv_bfloat16* __restrict__ o5)
{
    int idx = blockIdx.x * 256 + threadIdx.x;
    if (idx < WP0) { wprep_one(w1, o1, idx, 1024, 512, 512, 3); return; }
    idx -= WP0;
    if (idx < WP1) { wprep_one(w2, o2, idx, 80, 1024, 1024, 1); return; }
    idx -= WP1;
    if (idx < WP2) { wprep_one(q1, o3, idx, 160, 80, 128, 3); return; }
    idx -= WP2;
    if (idx < WP3) { wprep_one(q2, o4, idx, 80, 160, 192, 1); return; }
    idx -= WP3;
    if (idx < WP4) { wprep_one(q3, o5, idx, 80, 80, 128, 1); }
}

// X (B, C, T) fp32 -> guarded [b*(T+1)+1+t][Cpad] bf16 (zero pad cols)
__global__ void __launch_bounds__(256) prep_xpose_kernel(const float* __restrict__ X,
                                                         __nv_bfloat16* __restrict__ Xt,
                                                         int C, int T, int Cpad)
{
    __shared__ float tile[32][33];
    const int b  = blockIdx.z;
    const int t0 = blockIdx.x * 32;
    const int c0 = blockIdx.y * 32;
    const int tx = threadIdx.x, ty = threadIdx.y;
    const float* xb = X + (size_t)b * C * T;
#pragma unroll
    for (int j = 0; j < 32; j += 8) {
        int c = c0 + ty + j, t = t0 + tx;
        tile[ty + j][tx] = (c < C && t < T) ? xb[(size_t)c * T + t] : 0.f;
    }
    __syncthreads();
    __nv_bfloat16* xo = Xt + ((size_t)b * (T + 1) + 1) * Cpad;
#pragma unroll
    for (int j = 0; j < 32; j += 8) {
        int t = t0 + ty + j, c = c0 + tx;
        if (t < T && c < Cpad) xo[(size_t)t * Cpad + c] = __float2bfloat16(tile[tx][ty + j]);
    }
}

// fused kp2 split-K reduce + key norms; warp per row (1600 rows)
__global__ void __launch_bounds__(256) reduce_kp2_norms_kernel(
    const float* __restrict__ part, const float* __restrict__ bias,
    __nv_bfloat16* __restrict__ keb, float* __restrict__ nk)
{
    const int lane = threadIdx.x & 31;
    const int row  = blockIdx.x * 8 + (threadIdx.x >> 5);
    float sq = 0.f;
#pragma unroll
    for (int k = 0; k < 3; k++) {
        int m = lane + k * 32;
        if (m < 80) {
            int idx = row * 80 + m;
            float v = part[idx] + part[128000 + idx] + part[256000 + idx]
                    + part[384000 + idx] + bias[m];
            keb[(size_t)row * 128 + m] = __float2bfloat16(v);
            sq = fmaf(v, v, sq);
        }
    }
#pragma unroll
    for (int o = 16; o > 0; o >>= 1) sq += __shfl_xor_sync(0xffffffffu, sq, o);
    if (lane == 0) nk[row] = sq;
}

// ================= generic time-major conv/GEMM on mma.sync ================
// CTA tile: 128 t x 80 m. 8 warps = 4(t) x 2(m); warp 32t x 40m (2x5 m16n8k16).
// OUT=0 bf16+bias(+relu); OUT=1 fp32+bias; OUT=2 fp32 partial (slice z).
// ZMODE=0: z = batch; ZMODE=1: z = K-slice (merged batch).
// L>0: A rows map i -> i + i/L + 1 (guarded input, 1-tap only).
// Fill descriptors hoisted as u32 BYTE OFFSETS (arrays < 4MB) to keep regs
// <=128 so 2 CTAs/SM co-reside (launch_bounds minBlocks=2).

template <int TAPS, bool RELU, int OUT, int ZMODE>
__global__ void __launch_bounds__(256, 2) convmma_kernel(
    const __nv_bfloat16* __restrict__ X, const __nv_bfloat16* __restrict__ W,
    const float* __restrict__ bias, void* __restrict__ Yv,
    int N_t, int Mtot, int Cpad, int nChunks, int wbstride, int ystride, int L)
{
    constexpr int PAD   = (TAPS - 1) / 2;
    constexpr int AROWS = 128 + TAPS - 1;
    constexpr int ABUF  = AROWS * 128;
    constexpr int BROWS = TAPS * 80;
    constexpr int BBUF  = BROWS * 128;
    constexpr int BUF   = ABUF + BBUF + 16;      // +16B trash slot per buffer
    constexpr int nA    = (AROWS * 8 + 255) / 256;
    constexpr int nB    = (BROWS * 8 + 255) / 256;

    extern __shared__ char smem[];
    const uint32_t sbase = smem_u32(smem);
    const int tid  = threadIdx.x;
    const int lane = tid & 31;
    const int wid  = tid >> 5;
    const int t0   = blockIdx.x * 128;
    const int m0   = blockIdx.y * 80;
    const int b    = ZMODE ? 0 : blockIdx.z;
    const int kb   = ZMODE ? blockIdx.z * nChunks : 0;

    const int t_off = (wid & 3) * 32;
    const int m_off = (wid >> 2) * 40;

    const char* xb = (const char*)(X + (size_t)b * N_t * Cpad);
    const char* wb = (const char*)(W + (size_t)b * wbstride);

    // ---- hoisted fill descriptors: u32 global-byte-offset + u32 smem-offset ----
    uint32_t gA[nA], sA[nA];
    uint32_t gB[nB], sB[nB];
    unsigned mA = 0, mB = 0;
#pragma unroll
    for (int k = 0; k < nA; k++) {
        int idx = tid + k * 256;
        if (idx < AROWS * 8) {
            int row = idx >> 3, seg = idx & 7;
            int t = t0 + row - PAD;
            int xrow; bool ok;
            if (TAPS == 3) {
                xrow = t < 0 ? 0 : (t >= N_t ? N_t - 1 : t);
                ok = true;
            } else {
                ok = t < N_t;
                int i = ok ? t : N_t - 1;
                xrow = L ? (i + i / L + 1) : i;
            }
            gA[k] = (uint32_t)xrow * (uint32_t)(Cpad * 2) + (uint32_t)(kb * 128 + seg * 16);
            sA[k] = row * 128 + ((seg ^ (row & 7)) * 16);
            if (ok) mA |= 1u << k;
        } else {
            gA[k] = 0;
            sA[k] = ABUF + BBUF;                 // trash
        }
    }
#pragma unroll
    for (int k = 0; k < nB; k++) {
        int idx = tid + k * 256;
        if (idx < BROWS * 8) {
            int row = idx >> 3, seg = idx & 7;
            int tap = row / 80;
            int m = m0 + (row - tap * 80);
            int mc = m < Mtot ? m : Mtot - 1;
            gB[k] = ((uint32_t)tap * (uint32_t)Mtot + (uint32_t)mc) * (uint32_t)(Cpad * 2)
                  + (uint32_t)(kb * 128 + seg * 16);
            sB[k] = ABUF + row * 128 + ((seg ^ (row & 7)) * 16);
            if (m < Mtot) mB |= 1u << k;
        } else {
            gB[k] = 0;
            sB[k] = ABUF + BBUF;                 // trash
        }
    }

    float acc[2][5][4];
#pragma unroll
    for (int mt = 0; mt < 2; mt++)
#pragma unroll
        for (int nt = 0; nt < 5; nt++)
#pragma unroll
            for (int r = 0; r < 4; r++) acc[mt][nt][r] = 0.f;

    auto fill = [&](int buf, int chunk) {
        const uint32_t base = sbase + buf * BUF;
        const uint32_t co = chunk * 128;
#pragma unroll
        for (int k = 0; k < nA; k++)
            cp16(base + sA[k], xb + gA[k] + co, ((mA >> k) & 1) << 4);
#pragma unroll
        for (int k = 0; k < nB; k++)
            cp16(base + sB[k], wb + gB[k] + co, ((mB >> k) & 1) << 4);
        CP_COMMIT();
    };

    fill(0, 0);
    const int matm = lane >> 3;
    const int lrow = lane & 7;

    for (int s = 0; s < nChunks; s++) {
        const int cur = s & 1;
        if (s + 1 < nChunks) {
            fill(cur ^ 1, s + 1);
            asm volatile("cp.async.wait_group 1;" ::: "memory");
        } else {
            asm volatile("cp.async.wait_group 0;" ::: "memory");
        }
        __syncthreads();

        const uint32_t aA = sbase + cur * BUF;
        const uint32_t aB = aA + ABUF;
#pragma unroll
        for (int tap = 0; tap < TAPS; tap++) {
#pragma unroll
            for (int ks = 0; ks < 4; ks++) {
                uint32_t afr[2][4];
#pragma unroll
                for (int mt = 0; mt < 2; mt++) {
                    int r = t_off + mt * 16 + (matm & 1) * 8 + lrow + tap;
                    int seg = ks * 2 + (matm >> 1);
                    ldmx4(afr[mt], aA + r * 128 + ((seg ^ (r & 7)) * 16));
                }
                uint32_t bfr[5][2];
#pragma unroll
                for (int np = 0; np < 2; np++) {            // nt pairs via x4
                    int r = tap * 80 + m_off + (2 * np + (matm >> 1)) * 8 + lrow;
                    int seg = ks * 2 + (matm & 1);
                    uint32_t tmp[4];
                    ldmx4(tmp, aB + r * 128 + ((seg ^ (r & 7)) * 16));
                    bfr[2 * np][0] = tmp[0]; bfr[2 * np][1] = tmp[1];
                    bfr[2 * np + 1][0] = tmp[2]; bfr[2 * np + 1][1] = tmp[3];
                }
                {                                            // nt = 4 via x2
                    int r = tap * 80 + m_off + 32 + lrow;
                    int seg = ks * 2 + (matm & 1);
                    ldmx2(bfr[4], aB + r * 128 + ((seg ^ (r & 7)) * 16));
                }
#pragma unroll
                for (int mt = 0; mt < 2; mt++)
#pragma unroll
                    for (int nt = 0; nt < 5; nt++)
                        mma16816(acc[mt][nt], afr[mt], bfr[nt]);
            }
        }
        __syncthreads();
    }

    // epilogue
    const int g = lane >> 2, tg = lane & 3;
#pragma unroll
    for (int mt = 0; mt < 2; mt++) {
#pragma unroll
        for (int half = 0; half < 2; half++) {
            const int t = t0 + t_off + mt * 16 + g + half * 8;
            if (t >= N_t) continue;
#pragma unroll
            for (int nt = 0; nt < 5; nt++) {
                const int m = m0 + m_off + nt * 8 + tg * 2;
                if (m >= Mtot) continue;
                if (OUT == 2) {
                    float2* y = (float2*)((float*)Yv +
                        ((size_t)blockIdx.z * N_t + t) * ystride + m);
                    *y = make_float2(acc[mt][nt][half * 2 + 0], acc[mt][nt][half * 2 + 1]);
                } else {
                    float v0 = acc[mt][nt][half * 2 + 0] + bias[m];
                    float v1 = acc[mt][nt][half * 2 + 1] + bias[m + 1];
                    if (RELU) { v0 = fmaxf(v0, 0.f); v1 = fmaxf(v1, 0.f); }
                    if (OUT == 0) {
                        __nv_bfloat162* y = (__nv_bfloat162*)
                            ((__nv_bfloat16*)Yv + ((size_t)b * N_t + t) * ystride + m);
                        *y = __floats2bfloat162_rn(v0, v1);
                    } else {
                        float2* y = (float2*)
                            ((float*)Yv + ((size_t)b * N_t + t) * ystride + m);
                        *y = make_float2(v0, v1);
                    }
                }
            }
        }
    }
}

// ===================== softmax stage: warp per row =========================
__global__ void __launch_bounds__(256)
attn2_kernel(const float* __restrict__ G, const float* __restrict__ nk,
             const __nv_bfloat16* __restrict__ qeb, const float* __restrict__ prior,
             const unsigned* __restrict__ mask, float* __restrict__ out)
{
    const int lane = threadIdx.x & 31;
    const int row  = blockIdx.x * 8 + (threadIdx.x >> 5);   // b*800+i
    const int b    = row / T1n;

    const __nv_bfloat162* q2 = (const __nv_bfloat162*)(qeb + (size_t)row * 128);
    float nq;
    {
        float2 v = __bfloat1622float2(q2[lane]);
        float s = v.x * v.x + v.y * v.y;
        if (lane < 8) {
            float2 w = __bfloat1622float2(q2[32 + lane]);
            s = fmaf(w.x, w.x, fmaf(w.y, w.y, s));
        }
#pragma unroll
        for (int o = 16; o > 0; o >>= 1) s += __shfl_xor_sync(0xffffffffu, s, o);
        nq = s;
    }

    const float* Grow = G + (size_t)row * T2n;
    const float* nkb  = nk + b * T2n;

    float sc[7];
#pragma unroll
    for (int k = 0; k < 7; k++) {
        int j = lane + k * 32;
        sc[k] = (j < T2n) ? -5e-4f * (nq + nkb[j] - 2.f * Grow[j]) : -1e30f;
    }
    float mx = sc[0];
#pragma unroll
    for (int k = 1; k < 7; k++) mx = fmaxf(mx, sc[k]);
#pragma unroll
    for (int o = 16; o > 0; o >>= 1) mx = fmaxf(mx, __shfl_xor_sync(0xffffffffu, mx, o));
    float se = 0.f;
#pragma unroll
    for (int k = 0; k < 7; k++) se += __expf(sc[k] - mx);
#pragma unroll
    for (int o = 16; o > 0; o >>= 1) se += __shfl_xor_sync(0xffffffffu, se, o);
    const float lse = mx + __logf(se);

    const size_t base = (size_t)row * T2n;
    const float* prow = prior + base;
    float lp[7];
    bool  keep[7];
#pragma unroll
    for (int k = 0; k < 7; k++) {
        int j = lane + k * 32;
        if (j < T2n) {
            lp[k] = sc[k] - lse + __logf(prow[j] + 1e-8f);
            out[(size_t)Bn * T1n * T2n + base + j] = lp[k];
            keep[k] = (mask[b * T2n + j] == 0u);
        } else { lp[k] = -1e30f; keep[k] = false; }
    }

    float m2 = -1e30f;
#pragma unroll
    for (int k = 0; k < 7; k++) if (keep[k]) m2 = fmaxf(m2, lp[k]);
#pragma unroll
    for (int o = 16; o > 0; o >>= 1) m2 = fmaxf(m2, __shfl_xor_sync(0xffffffffu, m2, o));
    float s2 = 0.f;
#pragma unroll
    for (int k = 0; k < 7; k++) if (keep[k]) s2 += __expf(lp[k] - m2);
#pragma unroll
    for (int o = 16; o > 0; o >>= 1) s2 += __shfl_xor_sync(0xffffffffu, s2, o);

#pragma unroll
    for (int k = 0; k < 7; k++) {
        int j = lane + k * 32;
        if (j < T2n)
            out[base + j] = keep[k] ? __expf(lp[k] - m2) / s2 : 0.f;
    }
}

// ---------------------------------------------------------------------------

static void* sym_addr(const void* sym)
{
    void* p = nullptr;
    cudaGetSymbolAddress(&p, sym);
    return p;
}

#define SMEM_T3 (2 * ((130 + 240) * 128 + 16))   // 94752
#define SMEM_T1 (2 * ((128 + 80) * 128 + 16))    // 53280

extern "C" void kernel_launch(void* const* d_in, const int* in_sizes, int n_in,
                              void* d_out, int out_size)
{
    const float*    queries = (const float*)d_in[0];
    const float*    keys    = (const float*)d_in[1];
    const unsigned* mask    = (const unsigned*)d_in[3];
    const float*    prior   = (const float*)d_in[4];
    const float*    kp_w1   = (const float*)d_in[5];
    const float*    kp_b1   = (const float*)d_in[6];
    const float*    kp_w2   = (const float*)d_in[7];
    const float*    kp_b2   = (const float*)d_in[8];
    const float*    qp_w1   = (const float*)d_in[9];
    const float*    qp_b1   = (const float*)d_in[10];
    const float*    qp_w2   = (const float*)d_in[11];
    const float*    qp_b2   = (const float*)d_in[12];
    const float*    qp_w3   = (const float*)d_in[13];
    const float*    qp_b3   = (const float*)d_in[14];
    float* out = (float*)d_out;

    __nv_bfloat16* xt  = (__nv_bfloat16*)sym_addr(g_xt);
    __nv_bfloat16* xq  = (__nv_bfloat16*)sym_addr(g_xq);
    __nv_bfloat16* h1  = (__nv_bfloat16*)sym_addr(g_h1);
    __nv_bfloat16* keb = (__nv_bfloat16*)sym_addr(g_keb);
    __nv_bfloat16* hq1 = (__nv_bfloat16*)sym_addr(g_hq1);
    __nv_bfloat16* hq2 = (__nv_bfloat16*)sym_addr(g_hq2);
    __nv_bfloat16* qeb = (__nv_bfloat16*)sym_addr(g_qeb);
    __nv_bfloat16* wt  = (__nv_bfloat16*)sym_addr(g_wt);
    __nv_bfloat16* wk2 = (__nv_bfloat16*)sym_addr(g_wk2);
    __nv_bfloat16* wq1 = (__nv_bfloat16*)sym_addr(g_wq1);
    __nv_bfloat16* wq2 = (__nv_bfloat16*)sym_addr(g_wq2);
    __nv_bfloat16* wq3 = (__nv_bfloat16*)sym_addr(g_wq3);
    float* part = (float*)sym_addr(g_part);
    float* G    = (float*)sym_addr(g_G);
    float* nk   = (float*)sym_addr(g_nk);
    float* zb   = (float*)sym_addr(g_zbias);

    static bool attr_set = false;
    if (!attr_set) {
        cudaFuncSetAttribute(convmma_kernel<3, true, 0, 0>,
                             cudaFuncAttributeMaxDynamicSharedMemorySize, SMEM_T3);
        cudaFuncSetAttribute(convmma_kernel<1, true, 0, 0>,
                             cudaFuncAttributeMaxDynamicSharedMemorySize, SMEM_T1);
        cudaFuncSetAttribute(convmma_kernel<1, false, 0, 0>,
                             cudaFuncAttributeMaxDynamicSharedMemorySize, SMEM_T1);
        cudaFuncSetAttribute(convmma_kernel<1, false, 1, 0>,
                             cudaFuncAttributeMaxDynamicSharedMemorySize, SMEM_T1);
        cudaFuncSetAttribute(convmma_kernel<1, false, 2, 1>,
                             cudaFuncAttributeMaxDynamicSharedMemorySize, SMEM_T1);
        attr_set = true;
    }

    // ---- preps ----
    prep_weights_kernel<<<(WP0 + WP1 + WP2 + WP3 + WP4 + 255) / 256, 256>>>(
        kp_w1, kp_w2, qp_w1, qp_w2, qp_w3, wt, wk2, wq1, wq2, wq3);
    prep_xpose_kernel<<<dim3(7, 16, 8), dim3(32, 8)>>>(keys, xt, 512, T2n, 512);
    prep_xpose_kernel<<<dim3(25, 4, 8), dim3(32, 8)>>>(queries, xq, 80, T1n, 128);

    // ---- key projection ----
    // kp1: guard-merged, N_t = 8*201+1 = 1609. grid (13 t, 13 m, 1)
    convmma_kernel<3, true, 0, 0><<<dim3(13, 13, 1), 256, SMEM_T3>>>(
        xt, wt, kp_b1, h1, 1609, 1024, 512, 8, 0, 1024, 0);
    // kp2: 1024->80, merged valid rows (1600), rowmap L=200, split-K x4
    convmma_kernel<1, false, 2, 1><<<dim3(13, 1, 4), 256, SMEM_T1>>>(
        h1, wk2, zb, part, 1600, 80, 1024, 4, 0, 80, 200);
    reduce_kp2_norms_kernel<<<200, 256>>>(part, kp_b2, keb, nk);

    // ---- query projection chain ----
    // qp1: guard-merged, N_t = 8*801+1 = 6409. grid (51, 2, 1)
    convmma_kernel<3, true, 0, 0><<<dim3(51, 2, 1), 256, SMEM_T3>>>(
        xq, wq1, qp_b1, hq1, 6409, 160, 128, 2, 0, 192, 0);
    // qp2: reads guarded hq1 via L=800, writes plain hq2
    convmma_kernel<1, true, 0, 0><<<dim3(50, 1, 1), 256, SMEM_T1>>>(
        hq1, wq2, qp_b2, hq2, 6400, 80, 192, 3, 0, 128, 800);
    // qp3: plain -> plain
    convmma_kernel<1, false, 0, 0><<<dim3(50, 1, 1), 256, SMEM_T1>>>(
        hq2, wq3, qp_b3, qeb, 6400, 80, 128, 2, 0, 128, 0);

    // ---- Gram matrix G = qe . ke^T (keb as per-batch "weights") ----
    convmma_kernel<1, false, 1, 0><<<dim3(7, 3, 8), 256, SMEM_T1>>>(
        qeb, keb, zb, G, 800, 200, 128, 2, 200 * 128, 200, 0);

    // ---- softmax stage ----
    attn2_kernel<<<800, 256>>>(G, nk, qeb, prior, mask, out);
}

// round 10
// speedup vs baseline: 10.4173x; 1.2143x over previous
#include <cuda_runtime.h>
#include <cuda_bf16.h>
#include <cstdint>

// ---------------------------------------------------------------------------
// ConvAttention, R9: R8 kernels + two-stream DAG (query-proj chain runs
// concurrently with key-proj chain via event fork/join inside graph capture).
// ---------------------------------------------------------------------------

#define Bn   8
#define T1n  800
#define T2n  200

// -------- scratch (device globals; zero-initialized, guards never written) --
__device__ __nv_bfloat16 g_xt [1664 * 512];      // keys guarded [1609+pad][512]
__device__ __nv_bfloat16 g_xq [6528 * 128];      // queries guarded [6409+pad][128]
__device__ __nv_bfloat16 g_h1 [1664 * 1024];     // kp1 out, guard layout
__device__ __nv_bfloat16 g_keb[1600 * 128];      // key emb plain (pads stay 0)
__device__ __nv_bfloat16 g_hq1[6528 * 192];      // qp1 out, guard layout
__device__ __nv_bfloat16 g_hq2[6400 * 128];      // qp2 out plain
__device__ __nv_bfloat16 g_qeb[6400 * 128];      // query emb plain
__device__ __nv_bfloat16 g_wt [3 * 1024 * 512];  // kp_w1 [tap][m][512]
__device__ __nv_bfloat16 g_wk2[80 * 1024];
__device__ __nv_bfloat16 g_wq1[3 * 160 * 128];
__device__ __nv_bfloat16 g_wq2[80 * 192];
__device__ __nv_bfloat16 g_wq3[80 * 128];
__device__ float g_part[4 * 1600 * 80];          // kp2 split-K partials
__device__ float g_G  [8 * 800 * 200];
__device__ float g_nk [8 * 200];
__device__ float g_zbias[256];

// ========================= inline PTX helpers ==============================

__device__ __forceinline__ uint32_t smem_u32(const void* p) {
    uint32_t a;
    asm("{ .reg .u64 t; cvta.to.shared.u64 t, %1; cvt.u32.u64 %0, t; }"
        : "=r"(a) : "l"(p));
    return a;
}
__device__ __forceinline__ void cp16(uint32_t dst, const void* src, int sz) {
    asm volatile("cp.async.cg.shared.global [%0], [%1], 16, %2;"
                 :: "r"(dst), "l"(src), "r"(sz) : "memory");
}
#define CP_COMMIT() asm volatile("cp.async.commit_group;" ::: "memory")

__device__ __forceinline__ void ldmx4(uint32_t* r, uint32_t addr) {
    asm volatile("ldmatrix.sync.aligned.m8n8.x4.shared.b16 {%0,%1,%2,%3}, [%4];"
                 : "=r"(r[0]), "=r"(r[1]), "=r"(r[2]), "=r"(r[3]) : "r"(addr));
}
__device__ __forceinline__ void ldmx2(uint32_t* r, uint32_t addr) {
    asm volatile("ldmatrix.sync.aligned.m8n8.x2.shared.b16 {%0,%1}, [%2];"
                 : "=r"(r[0]), "=r"(r[1]) : "r"(addr));
}
__device__ __forceinline__ void mma16816(float* c, const uint32_t* a, const uint32_t* bq) {
    asm volatile(
        "mma.sync.aligned.m16n8k16.row.col.f32.bf16.bf16.f32 "
        "{%0,%1,%2,%3}, {%4,%5,%6,%7}, {%8,%9}, {%0,%1,%2,%3};"
        : "+f"(c[0]), "+f"(c[1]), "+f"(c[2]), "+f"(c[3])
        : "r"(a[0]), "r"(a[1]), "r"(a[2]), "r"(a[3]), "r"(bq[0]), "r"(bq[1]));
}

// ============================ prep kernels =================================

__device__ __forceinline__ void wprep_one(const float* W, __nv_bfloat16* Wt,
                                          int idx, int M, int Cin, int Cpad, int taps)
{
    int c = idx % Cpad;
    int r = idx / Cpad;
    int m = r % M;
    int tap = r / M;
    float v = (c < Cin) ? W[((size_t)m * Cin + c) * taps + tap] : 0.f;
    Wt[idx] = __float2bfloat16(v);
}

#define WP0 (3 * 1024 * 512)
#define WP1 (80 * 1024)
#define WP2 (3 * 160 * 128)
#define WP3 (80 * 192)
#define WP4 (80 * 128)
__global__ void __launch_bounds__(256) prep_weights_kernel(
    const float* __restrict__ w1, const float* __restrict__ w2,
    const float* __restrict__ q1, const float* __restrict__ q2,
    const float* __restrict__ q3,
    __nv_bfloat16* __restrict__ o1, __nv_bfloat16* __restrict__ o2,
    __nv_bfloat16* __restrict__ o3, __nv_bfloat16* __restrict__ o4,
    __nv_bfloat16* __restrict__ o5)
{
    int idx = blockIdx.x * 256 + threadIdx.x;
    if (idx < WP0) { wprep_one(w1, o1, idx, 1024, 512, 512, 3); return; }
    idx -= WP0;
    if (idx < WP1) { wprep_one(w2, o2, idx, 80, 1024, 1024, 1); return; }
    idx -= WP1;
    if (idx < WP2) { wprep_one(q1, o3, idx, 160, 80, 128, 3); return; }
    idx -= WP2;
    if (idx < WP3) { wprep_one(q2, o4, idx, 80, 160, 192, 1); return; }
    idx -= WP3;
    if (idx < WP4) { wprep_one(q3, o5, idx, 80, 80, 128, 1); }
}

// X (B, C, T) fp32 -> guarded [b*(T+1)+1+t][Cpad] bf16 (zero pad cols)
__global__ void __launch_bounds__(256) prep_xpose_kernel(const float* __restrict__ X,
                                                         __nv_bfloat16* __restrict__ Xt,
                                                         int C, int T, int Cpad)
{
    __shared__ float tile[32][33];
    const int b  = blockIdx.z;
    const int t0 = blockIdx.x * 32;
    const int c0 = blockIdx.y * 32;
    const int tx = threadIdx.x, ty = threadIdx.y;
    const float* xb = X + (size_t)b * C * T;
#pragma unroll
    for (int j = 0; j < 32; j += 8) {
        int c = c0 + ty + j, t = t0 + tx;
        tile[ty + j][tx] = (c < C && t < T) ? xb[(size_t)c * T + t] : 0.f;
    }
    __syncthreads();
    __nv_bfloat16* xo = Xt + ((size_t)b * (T + 1) + 1) * Cpad;
#pragma unroll
    for (int j = 0; j < 32; j += 8) {
        int t = t0 + ty + j, c = c0 + tx;
        if (t < T && c < Cpad) xo[(size_t)t * Cpad + c] = __float2bfloat16(tile[tx][ty + j]);
    }
}

// fused kp2 split-K reduce + key norms; warp per row (1600 rows)
__global__ void __launch_bounds__(256) reduce_kp2_norms_kernel(
    const float* __restrict__ part, const float* __restrict__ bias,
    __nv_bfloat16* __restrict__ keb, float* __restrict__ nk)
{
    const int lane = threadIdx.x & 31;
    const int row  = blockIdx.x * 8 + (threadIdx.x >> 5);
    float sq = 0.f;
#pragma unroll
    for (int k = 0; k < 3; k++) {
        int m = lane + k * 32;
        if (m < 80) {
            int idx = row * 80 + m;
            float v = part[idx] + part[128000 + idx] + part[256000 + idx]
                    + part[384000 + idx] + bias[m];
            keb[(size_t)row * 128 + m] = __float2bfloat16(v);
            sq = fmaf(v, v, sq);
        }
    }
#pragma unroll
    for (int o = 16; o > 0; o >>= 1) sq += __shfl_xor_sync(0xffffffffu, sq, o);
    if (lane == 0) nk[row] = sq;
}

// ================= generic time-major conv/GEMM on mma.sync ================
// CTA tile: 128 t x 80 m. 8 warps = 4(t) x 2(m); warp 32t x 40m (2x5 m16n8k16).
// OUT=0 bf16+bias(+relu); OUT=1 fp32+bias; OUT=2 fp32 partial (slice z).
// ZMODE=0: z = batch; ZMODE=1: z = K-slice (merged batch).
// L>0: A rows map i -> i + i/L + 1 (guarded input, 1-tap only).

template <int TAPS, bool RELU, int OUT, int ZMODE>
__global__ void __launch_bounds__(256, 2) convmma_kernel(
    const __nv_bfloat16* __restrict__ X, const __nv_bfloat16* __restrict__ W,
    const float* __restrict__ bias, void* __restrict__ Yv,
    int N_t, int Mtot, int Cpad, int nChunks, int wbstride, int ystride, int L)
{
    constexpr int PAD   = (TAPS - 1) / 2;
    constexpr int AROWS = 128 + TAPS - 1;
    constexpr int ABUF  = AROWS * 128;
    constexpr int BROWS = TAPS * 80;
    constexpr int BBUF  = BROWS * 128;
    constexpr int BUF   = ABUF + BBUF + 16;      // +16B trash slot per buffer
    constexpr int nA    = (AROWS * 8 + 255) / 256;
    constexpr int nB    = (BROWS * 8 + 255) / 256;

    extern __shared__ char smem[];
    const uint32_t sbase = smem_u32(smem);
    const int tid  = threadIdx.x;
    const int lane = tid & 31;
    const int wid  = tid >> 5;
    const int t0   = blockIdx.x * 128;
    const int m0   = blockIdx.y * 80;
    const int b    = ZMODE ? 0 : blockIdx.z;
    const int kb   = ZMODE ? blockIdx.z * nChunks : 0;

    const int t_off = (wid & 3) * 32;
    const int m_off = (wid >> 2) * 40;

    const char* xb = (const char*)(X + (size_t)b * N_t * Cpad);
    const char* wb = (const char*)(W + (size_t)b * wbstride);

    // ---- hoisted fill descriptors: u32 global-byte-offset + u32 smem-offset ----
    uint32_t gA[nA], sA[nA];
    uint32_t gB[nB], sB[nB];
    unsigned mA = 0, mB = 0;
#pragma unroll
    for (int k = 0; k < nA; k++) {
        int idx = tid + k * 256;
        if (idx < AROWS * 8) {
            int row = idx >> 3, seg = idx & 7;
            int t = t0 + row - PAD;
            int xrow; bool ok;
            if (TAPS == 3) {
                xrow = t < 0 ? 0 : (t >= N_t ? N_t - 1 : t);
                ok = true;
            } else {
                ok = t < N_t;
                int i = ok ? t : N_t - 1;
                xrow = L ? (i + i / L + 1) : i;
            }
            gA[k] = (uint32_t)xrow * (uint32_t)(Cpad * 2) + (uint32_t)(kb * 128 + seg * 16);
            sA[k] = row * 128 + ((seg ^ (row & 7)) * 16);
            if (ok) mA |= 1u << k;
        } else {
            gA[k] = 0;
            sA[k] = ABUF + BBUF;                 // trash
        }
    }
#pragma unroll
    for (int k = 0; k < nB; k++) {
        int idx = tid + k * 256;
        if (idx < BROWS * 8) {
            int row = idx >> 3, seg = idx & 7;
            int tap = row / 80;
            int m = m0 + (row - tap * 80);
            int mc = m < Mtot ? m : Mtot - 1;
            gB[k] = ((uint32_t)tap * (uint32_t)Mtot + (uint32_t)mc) * (uint32_t)(Cpad * 2)
                  + (uint32_t)(kb * 128 + seg * 16);
            sB[k] = ABUF + row * 128 + ((seg ^ (row & 7)) * 16);
            if (m < Mtot) mB |= 1u << k;
        } else {
            gB[k] = 0;
            sB[k] = ABUF + BBUF;                 // trash
        }
    }

    float acc[2][5][4];
#pragma unroll
    for (int mt = 0; mt < 2; mt++)
#pragma unroll
        for (int nt = 0; nt < 5; nt++)
#pragma unroll
            for (int r = 0; r < 4; r++) acc[mt][nt][r] = 0.f;

    auto fill = [&](int buf, int chunk) {
        const uint32_t base = sbase + buf * BUF;
        const uint32_t co = chunk * 128;
#pragma unroll
        for (int k = 0; k < nA; k++)
            cp16(base + sA[k], xb + gA[k] + co, ((mA >> k) & 1) << 4);
#pragma unroll
        for (int k = 0; k < nB; k++)
            cp16(base + sB[k], wb + gB[k] + co, ((mB >> k) & 1) << 4);
        CP_COMMIT();
    };

    fill(0, 0);
    const int matm = lane >> 3;
    const int lrow = lane & 7;

    for (int s = 0; s < nChunks; s++) {
        const int cur = s & 1;
        if (s + 1 < nChunks) {
            fill(cur ^ 1, s + 1);
            asm volatile("cp.async.wait_group 1;" ::: "memory");
        } else {
            asm volatile("cp.async.wait_group 0;" ::: "memory");
        }
        __syncthreads();

        const uint32_t aA = sbase + cur * BUF;
        const uint32_t aB = aA + ABUF;
#pragma unroll
        for (int tap = 0; tap < TAPS; tap++) {
#pragma unroll
            for (int ks = 0; ks < 4; ks++) {
                uint32_t afr[2][4];
#pragma unroll
                for (int mt = 0; mt < 2; mt++) {
                    int r = t_off + mt * 16 + (matm & 1) * 8 + lrow + tap;
                    int seg = ks * 2 + (matm >> 1);
                    ldmx4(afr[mt], aA + r * 128 + ((seg ^ (r & 7)) * 16));
                }
                uint32_t bfr[5][2];
#pragma unroll
                for (int np = 0; np < 2; np++) {            // nt pairs via x4
                    int r = tap * 80 + m_off + (2 * np + (matm >> 1)) * 8 + lrow;
                    int seg = ks * 2 + (matm & 1);
                    uint32_t tmp[4];
                    ldmx4(tmp, aB + r * 128 + ((seg ^ (r & 7)) * 16));
                    bfr[2 * np][0] = tmp[0]; bfr[2 * np][1] = tmp[1];
                    bfr[2 * np + 1][0] = tmp[2]; bfr[2 * np + 1][1] = tmp[3];
                }
                {                                            // nt = 4 via x2
                    int r = tap * 80 + m_off + 32 + lrow;
                    int seg = ks * 2 + (matm & 1);
                    ldmx2(bfr[4], aB + r * 128 + ((seg ^ (r & 7)) * 16));
                }
#pragma unroll
                for (int mt = 0; mt < 2; mt++)
#pragma unroll
                    for (int nt = 0; nt < 5; nt++)
                        mma16816(acc[mt][nt], afr[mt], bfr[nt]);
            }
        }
        __syncthreads();
    }

    // epilogue
    const int g = lane >> 2, tg = lane & 3;
#pragma unroll
    for (int mt = 0; mt < 2; mt++) {
#pragma unroll
        for (int half = 0; half < 2; half++) {
            const int t = t0 + t_off + mt * 16 + g + half * 8;
            if (t >= N_t) continue;
#pragma unroll
            for (int nt = 0; nt < 5; nt++) {
                const int m = m0 + m_off + nt * 8 + tg * 2;
                if (m >= Mtot) continue;
                if (OUT == 2) {
                    float2* y = (float2*)((float*)Yv +
                        ((size_t)blockIdx.z * N_t + t) * ystride + m);
                    *y = make_float2(acc[mt][nt][half * 2 + 0], acc[mt][nt][half * 2 + 1]);
                } else {
                    float v0 = acc[mt][nt][half * 2 + 0] + bias[m];
                    float v1 = acc[mt][nt][half * 2 + 1] + bias[m + 1];
                    if (RELU) { v0 = fmaxf(v0, 0.f); v1 = fmaxf(v1, 0.f); }
                    if (OUT == 0) {
                        __nv_bfloat162* y = (__nv_bfloat162*)
                            ((__nv_bfloat16*)Yv + ((size_t)b * N_t + t) * ystride + m);
                        *y = __floats2bfloat162_rn(v0, v1);
                    } else {
                        float2* y = (float2*)
                            ((float*)Yv + ((size_t)b * N_t + t) * ystride + m);
                        *y = make_float2(v0, v1);
                    }
                }
            }
        }
    }
}

// ===================== softmax stage: warp per row =========================
__global__ void __launch_bounds__(256)
attn2_kernel(const float* __restrict__ G, const float* __restrict__ nk,
             const __nv_bfloat16* __restrict__ qeb, const float* __restrict__ prior,
             const unsigned* __restrict__ mask, float* __restrict__ out)
{
    const int lane = threadIdx.x & 31;
    const int row  = blockIdx.x * 8 + (threadIdx.x >> 5);   // b*800+i
    const int b    = row / T1n;

    const __nv_bfloat162* q2 = (const __nv_bfloat162*)(qeb + (size_t)row * 128);
    float nq;
    {
        float2 v = __bfloat1622float2(q2[lane]);
        float s = v.x * v.x + v.y * v.y;
        if (lane < 8) {
            float2 w = __bfloat1622float2(q2[32 + lane]);
            s = fmaf(w.x, w.x, fmaf(w.y, w.y, s));
        }
#pragma unroll
        for (int o = 16; o > 0; o >>= 1) s += __shfl_xor_sync(0xffffffffu, s, o);
        nq = s;
    }

    const float* Grow = G + (size_t)row * T2n;
    const float* nkb  = nk + b * T2n;

    float sc[7];
#pragma unroll
    for (int k = 0; k < 7; k++) {
        int j = lane + k * 32;
        sc[k] = (j < T2n) ? -5e-4f * (nq + nkb[j] - 2.f * Grow[j]) : -1e30f;
    }
    float mx = sc[0];
#pragma unroll
    for (int k = 1; k < 7; k++) mx = fmaxf(mx, sc[k]);
#pragma unroll
    for (int o = 16; o > 0; o >>= 1) mx = fmaxf(mx, __shfl_xor_sync(0xffffffffu, mx, o));
    float se = 0.f;
#pragma unroll
    for (int k = 0; k < 7; k++) se += __expf(sc[k] - mx);
#pragma unroll
    for (int o = 16; o > 0; o >>= 1) se += __shfl_xor_sync(0xffffffffu, se, o);
    const float lse = mx + __logf(se);

    const size_t base = (size_t)row * T2n;
    const float* prow = prior + base;
    float lp[7];
    bool  keep[7];
#pragma unroll
    for (int k = 0; k < 7; k++) {
        int j = lane + k * 32;
        if (j < T2n) {
            lp[k] = sc[k] - lse + __logf(prow[j] + 1e-8f);
            out[(size_t)Bn * T1n * T2n + base + j] = lp[k];
            keep[k] = (mask[b * T2n + j] == 0u);
        } else { lp[k] = -1e30f; keep[k] = false; }
    }

    float m2 = -1e30f;
#pragma unroll
    for (int k = 0; k < 7; k++) if (keep[k]) m2 = fmaxf(m2, lp[k]);
#pragma unroll
    for (int o = 16; o > 0; o >>= 1) m2 = fmaxf(m2, __shfl_xor_sync(0xffffffffu, m2, o));
    float s2 = 0.f;
#pragma unroll
    for (int k = 0; k < 7; k++) if (keep[k]) s2 += __expf(lp[k] - m2);
#pragma unroll
    for (int o = 16; o > 0; o >>= 1) s2 += __shfl_xor_sync(0xffffffffu, s2, o);

#pragma unroll
    for (int k = 0; k < 7; k++) {
        int j = lane + k * 32;
        if (j < T2n)
            out[base + j] = keep[k] ? __expf(lp[k] - m2) / s2 : 0.f;
    }
}

// ---------------------------------------------------------------------------

static void* sym_addr(const void* sym)
{
    void* p = nullptr;
    cudaGetSymbolAddress(&p, sym);
    return p;
}

#define SMEM_T3 (2 * ((130 + 240) * 128 + 16))   // 94752
#define SMEM_T1 (2 * ((128 + 80) * 128 + 16))    // 53280

extern "C" void kernel_launch(void* const* d_in, const int* in_sizes, int n_in,
                              void* d_out, int out_size)
{
    const float*    queries = (const float*)d_in[0];
    const float*    keys    = (const float*)d_in[1];
    const unsigned* mask    = (const unsigned*)d_in[3];
    const float*    prior   = (const float*)d_in[4];
    const float*    kp_w1   = (const float*)d_in[5];
    const float*    kp_b1   = (const float*)d_in[6];
    const float*    kp_w2   = (const float*)d_in[7];
    const float*    kp_b2   = (const float*)d_in[8];
    const float*    qp_w1   = (const float*)d_in[9];
    const float*    qp_b1   = (const float*)d_in[10];
    const float*    qp_w2   = (const float*)d_in[11];
    const float*    qp_b2   = (const float*)d_in[12];
    const float*    qp_w3   = (const float*)d_in[13];
    const float*    qp_b3   = (const float*)d_in[14];
    float* out = (float*)d_out;

    __nv_bfloat16* xt  = (__nv_bfloat16*)sym_addr(g_xt);
    __nv_bfloat16* xq  = (__nv_bfloat16*)sym_addr(g_xq);
    __nv_bfloat16* h1  = (__nv_bfloat16*)sym_addr(g_h1);
    __nv_bfloat16* keb = (__nv_bfloat16*)sym_addr(g_keb);
    __nv_bfloat16* hq1 = (__nv_bfloat16*)sym_addr(g_hq1);
    __nv_bfloat16* hq2 = (__nv_bfloat16*)sym_addr(g_hq2);
    __nv_bfloat16* qeb = (__nv_bfloat16*)sym_addr(g_qeb);
    __nv_bfloat16* wt  = (__nv_bfloat16*)sym_addr(g_wt);
    __nv_bfloat16* wk2 = (__nv_bfloat16*)sym_addr(g_wk2);
    __nv_bfloat16* wq1 = (__nv_bfloat16*)sym_addr(g_wq1);
    __nv_bfloat16* wq2 = (__nv_bfloat16*)sym_addr(g_wq2);
    __nv_bfloat16* wq3 = (__nv_bfloat16*)sym_addr(g_wq3);
    float* part = (float*)sym_addr(g_part);
    float* G    = (float*)sym_addr(g_G);
    float* nk   = (float*)sym_addr(g_nk);
    float* zb   = (float*)sym_addr(g_zbias);

    static cudaStream_t s1;
    static cudaEvent_t evF, evQ;
    static bool init_done = false;
    if (!init_done) {
        cudaStreamCreateWithFlags(&s1, cudaStreamNonBlocking);
        cudaEventCreateWithFlags(&evF, cudaEventDisableTiming);
        cudaEventCreateWithFlags(&evQ, cudaEventDisableTiming);
        cudaFuncSetAttribute(convmma_kernel<3, true, 0, 0>,
                             cudaFuncAttributeMaxDynamicSharedMemorySize, SMEM_T3);
        cudaFuncSetAttribute(convmma_kernel<1, true, 0, 0>,
                             cudaFuncAttributeMaxDynamicSharedMemorySize, SMEM_T1);
        cudaFuncSetAttribute(convmma_kernel<1, false, 0, 0>,
                             cudaFuncAttributeMaxDynamicSharedMemorySize, SMEM_T1);
        cudaFuncSetAttribute(convmma_kernel<1, false, 1, 0>,
                             cudaFuncAttributeMaxDynamicSharedMemorySize, SMEM_T1);
        cudaFuncSetAttribute(convmma_kernel<1, false, 2, 1>,
                             cudaFuncAttributeMaxDynamicSharedMemorySize, SMEM_T1);
        init_done = true;
    }

    // ---- stream 0: preps needed by both chains ----
    prep_weights_kernel<<<(WP0 + WP1 + WP2 + WP3 + WP4 + 255) / 256, 256>>>(
        kp_w1, kp_w2, qp_w1, qp_w2, qp_w3, wt, wk2, wq1, wq2, wq3);
    prep_xpose_kernel<<<dim3(25, 4, 8), dim3(32, 8)>>>(queries, xq, 80, T1n, 128);

    // ---- fork: query-projection chain on side stream s1 ----
    cudaEventRecord(evF, 0);
    cudaStreamWaitEvent(s1, evF, 0);
    convmma_kernel<3, true, 0, 0><<<dim3(51, 2, 1), 256, SMEM_T3, s1>>>(
        xq, wq1, qp_b1, hq1, 6409, 160, 128, 2, 0, 192, 0);
    convmma_kernel<1, true, 0, 0><<<dim3(50, 1, 1), 256, SMEM_T1, s1>>>(
        hq1, wq2, qp_b2, hq2, 6400, 80, 192, 3, 0, 128, 800);
    convmma_kernel<1, false, 0, 0><<<dim3(50, 1, 1), 256, SMEM_T1, s1>>>(
        hq2, wq3, qp_b3, qeb, 6400, 80, 128, 2, 0, 128, 0);
    cudaEventRecord(evQ, s1);

    // ---- stream 0: key-projection chain (concurrent with s1) ----
    prep_xpose_kernel<<<dim3(7, 16, 8), dim3(32, 8)>>>(keys, xt, 512, T2n, 512);
    convmma_kernel<3, true, 0, 0><<<dim3(13, 13, 1), 256, SMEM_T3>>>(
        xt, wt, kp_b1, h1, 1609, 1024, 512, 8, 0, 1024, 0);
    convmma_kernel<1, false, 2, 1><<<dim3(13, 1, 4), 256, SMEM_T1>>>(
        h1, wk2, zb, part, 1600, 80, 1024, 4, 0, 80, 200);
    reduce_kp2_norms_kernel<<<200, 256>>>(part, kp_b2, keb, nk);

    // ---- join, then Gram + softmax ----
    cudaStreamWaitEvent(0, evQ, 0);
    convmma_kernel<1, false, 1, 0><<<dim3(7, 3, 8), 256, SMEM_T1>>>(
        qeb, keb, zb, G, 800, 200, 128, 2, 200 * 128, 200, 0);
    attn2_kernel<<<800, 256>>>(G, nk, qeb, prior, mask, out);
}

// round 11
// speedup vs baseline: 11.1692x; 1.0722x over previous
#include <cuda_runtime.h>
#include <cuda_bf16.h>
#include <cstdint>

// ---------------------------------------------------------------------------
// ConvAttention, R10: 3-stream DAG. Critical path = prep_wt -> kp1 ->
// kp2(splitK8) -> reduce -> Gram -> attn2. Side: xpose_k (s2); query chain +
// log-prior precompute (s1). convmma kernels unchanged from R8.
// ---------------------------------------------------------------------------

#define Bn   8
#define T1n  800
#define T2n  200

// -------- scratch (device globals; zero-initialized, guards never written) --
__device__ __nv_bfloat16 g_xt [1664 * 512];      // keys guarded [1609+pad][512]
__device__ __nv_bfloat16 g_xq [6528 * 128];      // queries guarded [6409+pad][128]
__device__ __nv_bfloat16 g_h1 [1664 * 1024];     // kp1 out, guard layout
__device__ __nv_bfloat16 g_keb[1600 * 128];      // key emb plain (pads stay 0)
__device__ __nv_bfloat16 g_hq1[6528 * 192];      // qp1 out, guard layout
__device__ __nv_bfloat16 g_hq2[6400 * 128];      // qp2 out plain
__device__ __nv_bfloat16 g_qeb[6400 * 128];      // query emb plain
__device__ __nv_bfloat16 g_wt [3 * 1024 * 512];  // kp_w1 [tap][m][512]
__device__ __nv_bfloat16 g_wk2[80 * 1024];
__device__ __nv_bfloat16 g_wq1[3 * 160 * 128];
__device__ __nv_bfloat16 g_wq2[80 * 192];
__device__ __nv_bfloat16 g_wq3[80 * 128];
__device__ float g_part[8 * 1600 * 80];          // kp2 split-K partials (8 slices)
__device__ float g_G  [8 * 800 * 200];
__device__ float g_LP [8 * 800 * 200];           // log(prior + 1e-8)
__device__ float g_nk [8 * 200];
__device__ float g_zbias[256];

// ========================= inline PTX helpers ==============================

__device__ __forceinline__ uint32_t smem_u32(const void* p) {
    uint32_t a;
    asm("{ .reg .u64 t; cvta.to.shared.u64 t, %1; cvt.u32.u64 %0, t; }"
        : "=r"(a) : "l"(p));
    return a;
}
__device__ __forceinline__ void cp16(uint32_t dst, const void* src, int sz) {
    asm volatile("cp.async.cg.shared.global [%0], [%1], 16, %2;"
                 :: "r"(dst), "l"(src), "r"(sz) : "memory");
}
#define CP_COMMIT() asm volatile("cp.async.commit_group;" ::: "memory")

__device__ __forceinline__ void ldmx4(uint32_t* r, uint32_t addr) {
    asm volatile("ldmatrix.sync.aligned.m8n8.x4.shared.b16 {%0,%1,%2,%3}, [%4];"
                 : "=r"(r[0]), "=r"(r[1]), "=r"(r[2]), "=r"(r[3]) : "r"(addr));
}
__device__ __forceinline__ void ldmx2(uint32_t* r, uint32_t addr) {
    asm volatile("ldmatrix.sync.aligned.m8n8.x2.shared.b16 {%0,%1}, [%2];"
                 : "=r"(r[0]), "=r"(r[1]) : "r"(addr));
}
__device__ __forceinline__ void mma16816(float* c, const uint32_t* a, const uint32_t* bq) {
    asm volatile(
        "mma.sync.aligned.m16n8k16.row.col.f32.bf16.bf16.f32 "
        "{%0,%1,%2,%3}, {%4,%5,%6,%7}, {%8,%9}, {%0,%1,%2,%3};"
        : "+f"(c[0]), "+f"(c[1]), "+f"(c[2]), "+f"(c[3])
        : "r"(a[0]), "r"(a[1]), "r"(a[2]), "r"(a[3]), "r"(bq[0]), "r"(bq[1]));
}

// ============================ prep kernels =================================

__device__ __forceinline__ void wprep_one(const float* W, __nv_bfloat16* Wt,
                                          int idx, int M, int Cin, int Cpad, int taps)
{
    int c = idx % Cpad;
    int r = idx / Cpad;
    int m = r % M;
    int tap = r / M;
    float v = (c < Cin) ? W[((size_t)m * Cin + c) * taps + tap] : 0.f;
    Wt[idx] = __float2bfloat16(v);
}

// kp_w1 (1024,512,3) fp32 -> g_wt [tap][m][c] bf16 (critical path)
__global__ void __launch_bounds__(256) prep_wt_kernel(const float* __restrict__ W,
                                                      __nv_bfloat16* __restrict__ Wt)
{
    int idx = blockIdx.x * 256 + threadIdx.x;          // idx = m*512 + c
    if (idx >= 1024 * 512) return;
    const float* s = W + (size_t)idx * 3;
    Wt[(size_t)idx]                    = __float2bfloat16(s[0]);
    Wt[(size_t)(1024 * 512) + idx]     = __float2bfloat16(s[1]);
    Wt[(size_t)(2 * 1024 * 512) + idx] = __float2bfloat16(s[2]);
}

// remaining weights (side stream)
#define WP1 (80 * 1024)
#define WP2 (3 * 160 * 128)
#define WP3 (80 * 192)
#define WP4 (80 * 128)
__global__ void __launch_bounds__(256) prep_wrest_kernel(
    const float* __restrict__ w2, const float* __restrict__ q1,
    const float* __restrict__ q2, const float* __restrict__ q3,
    __nv_bfloat16* __restrict__ o2, __nv_bfloat16* __restrict__ o3,
    __nv_bfloat16* __restrict__ o4, __nv_bfloat16* __restrict__ o5)
{
    int idx = blockIdx.x * 256 + threadIdx.x;
    if (idx < WP1) { wprep_one(w2, o2, idx, 80, 1024, 1024, 1); return; }
    idx -= WP1;
    if (idx < WP2) { wprep_one(q1, o3, idx, 160, 80, 128, 3); return; }
    idx -= WP2;
    if (idx < WP3) { wprep_one(q2, o4, idx, 80, 160, 192, 1); return; }
    idx -= WP3;
    if (idx < WP4) { wprep_one(q3, o5, idx, 80, 80, 128, 1); }
}

// X (B, C, T) fp32 -> guarded [b*(T+1)+1+t][Cpad] bf16 (zero pad cols)
__global__ void __launch_bounds__(256) prep_xpose_kernel(const float* __restrict__ X,
                                                         __nv_bfloat16* __restrict__ Xt,
                                                         int C, int T, int Cpad)
{
    __shared__ float tile[32][33];
    const int b  = blockIdx.z;
    const int t0 = blockIdx.x * 32;
    const int c0 = blockIdx.y * 32;
    const int tx = threadIdx.x, ty = threadIdx.y;
    const float* xb = X + (size_t)b * C * T;
#pragma unroll
    for (int j = 0; j < 32; j += 8) {
        int c = c0 + ty + j, t = t0 + tx;
        tile[ty + j][tx] = (c < C && t < T) ? xb[(size_t)c * T + t] : 0.f;
    }
    __syncthreads();
    __nv_bfloat16* xo = Xt + ((size_t)b * (T + 1) + 1) * Cpad;
#pragma unroll
    for (int j = 0; j < 32; j += 8) {
        int t = t0 + ty + j, c = c0 + tx;
        if (t < T && c < Cpad) xo[(size_t)t * Cpad + c] = __float2bfloat16(tile[tx][ty + j]);
    }
}

// log(prior + 1e-8), vectorized (side stream; hides under kp1)
__global__ void __launch_bounds__(256) prep_logprior_kernel(const float4* __restrict__ P,
                                                            float4* __restrict__ LP)
{
    int i = blockIdx.x * 256 + threadIdx.x;
    if (i >= 8 * 800 * 200 / 4) return;
    float4 p = P[i];
    float4 r;
    r.x = __logf(p.x + 1e-8f);
    r.y = __logf(p.y + 1e-8f);
    r.z = __logf(p.z + 1e-8f);
    r.w = __logf(p.w + 1e-8f);
    LP[i] = r;
}

// fused kp2 split-K(8) reduce + key norms; warp per row (1600 rows)
__global__ void __launch_bounds__(256) reduce_kp2_norms_kernel(
    const float* __restrict__ part, const float* __restrict__ bias,
    __nv_bfloat16* __restrict__ keb, float* __restrict__ nk)
{
    const int lane = threadIdx.x & 31;
    const int row  = blockIdx.x * 8 + (threadIdx.x >> 5);
    float sq = 0.f;
#pragma unroll
    for (int k = 0; k < 3; k++) {
        int m = lane + k * 32;
        if (m < 80) {
            int idx = row * 80 + m;
            float v = bias[m];
#pragma unroll
            for (int s = 0; s < 8; s++) v += part[s * 128000 + idx];
            keb[(size_t)row * 128 + m] = __float2bfloat16(v);
            sq = fmaf(v, v, sq);
        }
    }
#pragma unroll
    for (int o = 16; o > 0; o >>= 1) sq += __shfl_xor_sync(0xffffffffu, sq, o);
    if (lane == 0) nk[row] = sq;
}

// ================= generic time-major conv/GEMM on mma.sync ================
// CTA tile: 128 t x 80 m. 8 warps = 4(t) x 2(m); warp 32t x 40m (2x5 m16n8k16).
// OUT=0 bf16+bias(+relu); OUT=1 fp32+bias; OUT=2 fp32 partial (slice z).
// ZMODE=0: z = batch; ZMODE=1: z = K-slice (merged batch).
// L>0: A rows map i -> i + i/L + 1 (guarded input, 1-tap only).

template <int TAPS, bool RELU, int OUT, int ZMODE>
__global__ void __launch_bounds__(256, 2) convmma_kernel(
    const __nv_bfloat16* __restrict__ X, const __nv_bfloat16* __restrict__ W,
    const float* __restrict__ bias, void* __restrict__ Yv,
    int N_t, int Mtot, int Cpad, int nChunks, int wbstride, int ystride, int L)
{
    constexpr int PAD   = (TAPS - 1) / 2;
    constexpr int AROWS = 128 + TAPS - 1;
    constexpr int ABUF  = AROWS * 128;
    constexpr int BROWS = TAPS * 80;
    constexpr int BBUF  = BROWS * 128;
    constexpr int BUF   = ABUF + BBUF + 16;      // +16B trash slot per buffer
    constexpr int nA    = (AROWS * 8 + 255) / 256;
    constexpr int nB    = (BROWS * 8 + 255) / 256;

    extern __shared__ char smem[];
    const uint32_t sbase = smem_u32(smem);
    const int tid  = threadIdx.x;
    const int lane = tid & 31;
    const int wid  = tid >> 5;
    const int t0   = blockIdx.x * 128;
    const int m0   = blockIdx.y * 80;
    const int b    = ZMODE ? 0 : blockIdx.z;
    const int kb   = ZMODE ? blockIdx.z * nChunks : 0;

    const int t_off = (wid & 3) * 32;
    const int m_off = (wid >> 2) * 40;

    const char* xb = (const char*)(X + (size_t)b * N_t * Cpad);
    const char* wb = (const char*)(W + (size_t)b * wbstride);

    // ---- hoisted fill descriptors: u32 global-byte-offset + u32 smem-offset ----
    uint32_t gA[nA], sA[nA];
    uint32_t gB[nB], sB[nB];
    unsigned mA = 0, mB = 0;
#pragma unroll
    for (int k = 0; k < nA; k++) {
        int idx = tid + k * 256;
        if (idx < AROWS * 8) {
            int row = idx >> 3, seg = idx & 7;
            int t = t0 + row - PAD;
            int xrow; bool ok;
            if (TAPS == 3) {
                xrow = t < 0 ? 0 : (t >= N_t ? N_t - 1 : t);
                ok = true;
            } else {
                ok = t < N_t;
                int i = ok ? t : N_t - 1;
                xrow = L ? (i + i / L + 1) : i;
            }
            gA[k] = (uint32_t)xrow * (uint32_t)(Cpad * 2) + (uint32_t)(kb * 128 + seg * 16);
            sA[k] = row * 128 + ((seg ^ (row & 7)) * 16);
            if (ok) mA |= 1u << k;
        } else {
            gA[k] = 0;
            sA[k] = ABUF + BBUF;                 // trash
        }
    }
#pragma unroll
    for (int k = 0; k < nB; k++) {
        int idx = tid + k * 256;
        if (idx < BROWS * 8) {
            int row = idx >> 3, seg = idx & 7;
            int tap = row / 80;
            int m = m0 + (row - tap * 80);
            int mc = m < Mtot ? m : Mtot - 1;
            gB[k] = ((uint32_t)tap * (uint32_t)Mtot + (uint32_t)mc) * (uint32_t)(Cpad * 2)
                  + (uint32_t)(kb * 128 + seg * 16);
            sB[k] = ABUF + row * 128 + ((seg ^ (row & 7)) * 16);
            if (m < Mtot) mB |= 1u << k;
        } else {
            gB[k] = 0;
            sB[k] = ABUF + BBUF;                 // trash
        }
    }

    float acc[2][5][4];
#pragma unroll
    for (int mt = 0; mt < 2; mt++)
#pragma unroll
        for (int nt = 0; nt < 5; nt++)
#pragma unroll
            for (int r = 0; r < 4; r++) acc[mt][nt][r] = 0.f;

    auto fill = [&](int buf, int chunk) {
        const uint32_t base = sbase + buf * BUF;
        const uint32_t co = chunk * 128;
#pragma unroll
        for (int k = 0; k < nA; k++)
            cp16(base + sA[k], xb + gA[k] + co, ((mA >> k) & 1) << 4);
#pragma unroll
        for (int k = 0; k < nB; k++)
            cp16(base + sB[k], wb + gB[k] + co, ((mB >> k) & 1) << 4);
        CP_COMMIT();
    };

    fill(0, 0);
    const int matm = lane >> 3;
    const int lrow = lane & 7;

    for (int s = 0; s < nChunks; s++) {
        const int cur = s & 1;
        if (s + 1 < nChunks) {
            fill(cur ^ 1, s + 1);
            asm volatile("cp.async.wait_group 1;" ::: "memory");
        } else {
            asm volatile("cp.async.wait_group 0;" ::: "memory");
        }
        __syncthreads();

        const uint32_t aA = sbase + cur * BUF;
        const uint32_t aB = aA + ABUF;
#pragma unroll
        for (int tap = 0; tap < TAPS; tap++) {
#pragma unroll
            for (int ks = 0; ks < 4; ks++) {
                uint32_t afr[2][4];
#pragma unroll
                for (int mt = 0; mt < 2; mt++) {
                    int r = t_off + mt * 16 + (matm & 1) * 8 + lrow + tap;
                    int seg = ks * 2 + (matm >> 1);
                    ldmx4(afr[mt], aA + r * 128 + ((seg ^ (r & 7)) * 16));
                }
                uint32_t bfr[5][2];
#pragma unroll
                for (int np = 0; np < 2; np++) {            // nt pairs via x4
                    int r = tap * 80 + m_off + (2 * np + (matm >> 1)) * 8 + lrow;
                    int seg = ks * 2 + (matm & 1);
                    uint32_t tmp[4];
                    ldmx4(tmp, aB + r * 128 + ((seg ^ (r & 7)) * 16));
                    bfr[2 * np][0] = tmp[0]; bfr[2 * np][1] = tmp[1];
                    bfr[2 * np + 1][0] = tmp[2]; bfr[2 * np + 1][1] = tmp[3];
                }
                {                                            // nt = 4 via x2
                    int r = tap * 80 + m_off + 32 + lrow;
                    int seg = ks * 2 + (matm & 1);
                    ldmx2(bfr[4], aB + r * 128 + ((seg ^ (r & 7)) * 16));
                }
#pragma unroll
                for (int mt = 0; mt < 2; mt++)
#pragma unroll
                    for (int nt = 0; nt < 5; nt++)
                        mma16816(acc[mt][nt], afr[mt], bfr[nt]);
            }
        }
        __syncthreads();
    }

    // epilogue
    const int g = lane >> 2, tg = lane & 3;
#pragma unroll
    for (int mt = 0; mt < 2; mt++) {
#pragma unroll
        for (int half = 0; half < 2; half++) {
            const int t = t0 + t_off + mt * 16 + g + half * 8;
            if (t >= N_t) continue;
#pragma unroll
            for (int nt = 0; nt < 5; nt++) {
                const int m = m0 + m_off + nt * 8 + tg * 2;
                if (m >= Mtot) continue;
                if (OUT == 2) {
                    float2* y = (float2*)((float*)Yv +
                        ((size_t)blockIdx.z * N_t + t) * ystride + m);
                    *y = make_float2(acc[mt][nt][half * 2 + 0], acc[mt][nt][half * 2 + 1]);
                } else {
                    float v0 = acc[mt][nt][half * 2 + 0] + bias[m];
                    float v1 = acc[mt][nt][half * 2 + 1] + bias[m + 1];
                    if (RELU) { v0 = fmaxf(v0, 0.f); v1 = fmaxf(v1, 0.f); }
                    if (OUT == 0) {
                        __nv_bfloat162* y = (__nv_bfloat162*)
                            ((__nv_bfloat16*)Yv + ((size_t)b * N_t + t) * ystride + m);
                        *y = __floats2bfloat162_rn(v0, v1);
                    } else {
                        float2* y = (float2*)
                            ((float*)Yv + ((size_t)b * N_t + t) * ystride + m);
                        *y = make_float2(v0, v1);
                    }
                }
            }
        }
    }
}

// ===================== softmax stage: warp per row =========================
__global__ void __launch_bounds__(256)
attn2_kernel(const float* __restrict__ G, const float* __restrict__ nk,
             const __nv_bfloat16* __restrict__ qeb, const float* __restrict__ LP,
             const unsigned* __restrict__ mask, float* __restrict__ out)
{
    const int lane = threadIdx.x & 31;
    const int row  = blockIdx.x * 8 + (threadIdx.x >> 5);   // b*800+i
    const int b    = row / T1n;

    const __nv_bfloat162* q2 = (const __nv_bfloat162*)(qeb + (size_t)row * 128);
    float nq;
    {
        float2 v = __bfloat1622float2(q2[lane]);
        float s = v.x * v.x + v.y * v.y;
        if (lane < 8) {
            float2 w = __bfloat1622float2(q2[32 + lane]);
            s = fmaf(w.x, w.x, fmaf(w.y, w.y, s));
        }
#pragma unroll
        for (int o = 16; o > 0; o >>= 1) s += __shfl_xor_sync(0xffffffffu, s, o);
        nq = s;
    }

    const float* Grow = G + (size_t)row * T2n;
    const float* nkb  = nk + b * T2n;

    float sc[7];
#pragma unroll
    for (int k = 0; k < 7; k++) {
        int j = lane + k * 32;
        sc[k] = (j < T2n) ? -5e-4f * (nq + nkb[j] - 2.f * Grow[j]) : -1e30f;
    }
    float mx = sc[0];
#pragma unroll
    for (int k = 1; k < 7; k++) mx = fmaxf(mx, sc[k]);
#pragma unroll
    for (int o = 16; o > 0; o >>= 1) mx = fmaxf(mx, __shfl_xor_sync(0xffffffffu, mx, o));
    float se = 0.f;
#pragma unroll
    for (int k = 0; k < 7; k++) se += __expf(sc[k] - mx);
#pragma unroll
    for (int o = 16; o > 0; o >>= 1) se += __shfl_xor_sync(0xffffffffu, se, o);
    const float lse = mx + __logf(se);

    const size_t base = (size_t)row * T2n;
    const float* lrow_p = LP + base;
    float lp[7];
    bool  keep[7];
#pragma unroll
    for (int k = 0; k < 7; k++) {
        int j = lane + k * 32;
        if (j < T2n) {
            lp[k] = sc[k] - lse + lrow_p[j];
            out[(size_t)Bn * T1n * T2n + base + j] = lp[k];
            keep[k] = (mask[b * T2n + j] == 0u);
        } else { lp[k] = -1e30f; keep[k] = false; }
    }

    float m2 = -1e30f;
#pragma unroll
    for (int k = 0; k < 7; k++) if (keep[k]) m2 = fmaxf(m2, lp[k]);
#pragma unroll
    for (int o = 16; o > 0; o >>= 1) m2 = fmaxf(m2, __shfl_xor_sync(0xffffffffu, m2, o));
    float s2 = 0.f;
#pragma unroll
    for (int k = 0; k < 7; k++) if (keep[k]) s2 += __expf(lp[k] - m2);
#pragma unroll
    for (int o = 16; o > 0; o >>= 1) s2 += __shfl_xor_sync(0xffffffffu, s2, o);

#pragma unroll
    for (int k = 0; k < 7; k++) {
        int j = lane + k * 32;
        if (j < T2n)
            out[base + j] = keep[k] ? __expf(lp[k] - m2) / s2 : 0.f;
    }
}

// ---------------------------------------------------------------------------

static void* sym_addr(const void* sym)
{
    void* p = nullptr;
    cudaGetSymbolAddress(&p, sym);
    return p;
}

#define SMEM_T3 (2 * ((130 + 240) * 128 + 16))   // 94752
#define SMEM_T1 (2 * ((128 + 80) * 128 + 16))    // 53280

extern "C" void kernel_launch(void* const* d_in, const int* in_sizes, int n_in,
                              void* d_out, int out_size)
{
    const float*    queries = (const float*)d_in[0];
    const float*    keys    = (const float*)d_in[1];
    const unsigned* mask    = (const unsigned*)d_in[3];
    const float*    prior   = (const float*)d_in[4];
    const float*    kp_w1   = (const float*)d_in[5];
    const float*    kp_b1   = (const float*)d_in[6];
    const float*    kp_w2   = (const float*)d_in[7];
    const float*    kp_b2   = (const float*)d_in[8];
    const float*    qp_w1   = (const float*)d_in[9];
    const float*    qp_b1   = (const float*)d_in[10];
    const float*    qp_w2   = (const float*)d_in[11];
    const float*    qp_b2   = (const float*)d_in[12];
    const float*    qp_w3   = (const float*)d_in[13];
    const float*    qp_b3   = (const float*)d_in[14];
    float* out = (float*)d_out;

    __nv_bfloat16* xt  = (__nv_bfloat16*)sym_addr(g_xt);
    __nv_bfloat16* xq  = (__nv_bfloat16*)sym_addr(g_xq);
    __nv_bfloat16* h1  = (__nv_bfloat16*)sym_addr(g_h1);
    __nv_bfloat16* keb = (__nv_bfloat16*)sym_addr(g_keb);
    __nv_bfloat16* hq1 = (__nv_bfloat16*)sym_addr(g_hq1);
    __nv_bfloat16* hq2 = (__nv_bfloat16*)sym_addr(g_hq2);
    __nv_bfloat16* qeb = (__nv_bfloat16*)sym_addr(g_qeb);
    __nv_bfloat16* wt  = (__nv_bfloat16*)sym_addr(g_wt);
    __nv_bfloat16* wk2 = (__nv_bfloat16*)sym_addr(g_wk2);
    __nv_bfloat16* wq1 = (__nv_bfloat16*)sym_addr(g_wq1);
    __nv_bfloat16* wq2 = (__nv_bfloat16*)sym_addr(g_wq2);
    __nv_bfloat16* wq3 = (__nv_bfloat16*)sym_addr(g_wq3);
    float* part = (float*)sym_addr(g_part);
    float* G    = (float*)sym_addr(g_G);
    float* LP   = (float*)sym_addr(g_LP);
    float* nk   = (float*)sym_addr(g_nk);
    float* zb   = (float*)sym_addr(g_zbias);

    static cudaStream_t s1, s2;
    static cudaEvent_t evRoot, evQ, evK;
    static bool init_done = false;
    if (!init_done) {
        cudaStreamCreateWithFlags(&s1, cudaStreamNonBlocking);
        cudaStreamCreateWithFlags(&s2, cudaStreamNonBlocking);
        cudaEventCreateWithFlags(&evRoot, cudaEventDisableTiming);
        cudaEventCreateWithFlags(&evQ, cudaEventDisableTiming);
        cudaEventCreateWithFlags(&evK, cudaEventDisableTiming);
        cudaFuncSetAttribute(convmma_kernel<3, true, 0, 0>,
                             cudaFuncAttributeMaxDynamicSharedMemorySize, SMEM_T3);
        cudaFuncSetAttribute(convmma_kernel<1, true, 0, 0>,
                             cudaFuncAttributeMaxDynamicSharedMemorySize, SMEM_T1);
        cudaFuncSetAttribute(convmma_kernel<1, false, 0, 0>,
                             cudaFuncAttributeMaxDynamicSharedMemorySize, SMEM_T1);
        cudaFuncSetAttribute(convmma_kernel<1, false, 1, 0>,
                             cudaFuncAttributeMaxDynamicSharedMemorySize, SMEM_T1);
        cudaFuncSetAttribute(convmma_kernel<1, false, 2, 1>,
                             cudaFuncAttributeMaxDynamicSharedMemorySize, SMEM_T1);
        init_done = true;
    }

    // ---- fork both side streams off the origin stream ----
    cudaEventRecord(evRoot, 0);
    cudaStreamWaitEvent(s1, evRoot, 0);
    cudaStreamWaitEvent(s2, evRoot, 0);

    // ---- s2: key transpose (parallel with prep_wt) ----
    prep_xpose_kernel<<<dim3(7, 16, 8), dim3(32, 8), 0, s2>>>(keys, xt, 512, T2n, 512);
    cudaEventRecord(evK, s2);

    // ---- s1: query side (hidden under key chain) ----
    prep_wrest_kernel<<<(WP1 + WP2 + WP3 + WP4 + 255) / 256, 256, 0, s1>>>(
        kp_w2, qp_w1, qp_w2, qp_w3, wk2, wq1, wq2, wq3);
    prep_xpose_kernel<<<dim3(25, 4, 8), dim3(32, 8), 0, s1>>>(queries, xq, 80, T1n, 128);
    convmma_kernel<3, true, 0, 0><<<dim3(51, 2, 1), 256, SMEM_T3, s1>>>(
        xq, wq1, qp_b1, hq1, 6409, 160, 128, 2, 0, 192, 0);
    convmma_kernel<1, true, 0, 0><<<dim3(50, 1, 1), 256, SMEM_T1, s1>>>(
        hq1, wq2, qp_b2, hq2, 6400, 80, 192, 3, 0, 128, 800);
    convmma_kernel<1, false, 0, 0><<<dim3(50, 1, 1), 256, SMEM_T1, s1>>>(
        hq2, wq3, qp_b3, qeb, 6400, 80, 128, 2, 0, 128, 0);
    prep_logprior_kernel<<<(8 * 800 * 200 / 4 + 255) / 256, 256, 0, s1>>>(
        (const float4*)prior, (float4*)LP);
    cudaEventRecord(evQ, s1);

    // ---- stream 0: key chain (critical path) ----
    prep_wt_kernel<<<2048, 256>>>(kp_w1, wt);
    cudaStreamWaitEvent(0, evK, 0);
    convmma_kernel<3, true, 0, 0><<<dim3(13, 13, 1), 256, SMEM_T3>>>(
        xt, wt, kp_b1, h1, 1609, 1024, 512, 8, 0, 1024, 0);
    convmma_kernel<1, false, 2, 1><<<dim3(13, 1, 8), 256, SMEM_T1>>>(
        h1, wk2, zb, part, 1600, 80, 1024, 2, 0, 80, 200);
    reduce_kp2_norms_kernel<<<200, 256>>>(part, kp_b2, keb, nk);

    // ---- join, then Gram + softmax ----
    cudaStreamWaitEvent(0, evQ, 0);
    convmma_kernel<1, false, 1, 0><<<dim3(7, 3, 8), 256, SMEM_T1>>>(
        qeb, keb, zb, G, 800, 200, 128, 2, 200 * 128, 200, 0);
    attn2_kernel<<<800, 256>>>(G, nk, qeb, LP, mask, out);
}